// round 2
// baseline (speedup 1.0000x reference)
#include <cuda_runtime.h>
#include <cuda_bf16.h>

#define NN 50000
#define EE 800000
#define KF 256          // IN_FEATS
#define HH 4
#define DD 32
#define HD 128          // H*D
#define NH 200000       // N*H

// ---------------- scratch (device globals; no allocation) ----------------
__device__ float g_ft[NN * HD];       // projected features [N, H*D]
__device__ float g_el[NH];            // left logits  [N, H]
__device__ float g_er[NH];            // right logits [N, H]
__device__ float g_s[NH];             // softmax denominators [N, H]
__device__ float g_ee[EE * HH];       // exp(edge score) [E, H]
__device__ int   g_deg[NN];           // in-degree histogram
__device__ int   g_rowstart[NN + 1];  // CSR offsets
__device__ int   g_cursor[NN];        // scatter cursors
__device__ int   g_csr[EE];           // edge ids grouped by dst

// ---------------- init: zero s and deg ----------------
__global__ void init_kernel() {
    int i = blockIdx.x * blockDim.x + threadIdx.x;
    if (i < NH) g_s[i] = 0.0f;
    if (i < NN) g_deg[i] = 0;
}

// ---------------- GEMM: g_ft = feat @ W  (fp32, 128x128x16 tiles) ----------------
__global__ __launch_bounds__(256) void gemm_kernel(const float* __restrict__ A,
                                                   const float* __restrict__ B) {
    __shared__ float As[16][128];   // [k][row]  (transposed A tile)
    __shared__ float Bs[16][128];   // [k][col]
    const int block_row = blockIdx.x * 128;
    const int tid = threadIdx.x;
    const int tx = tid & 15;   // column group
    const int ty = tid >> 4;   // row group

    float acc[8][8];
#pragma unroll
    for (int i = 0; i < 8; i++)
#pragma unroll
        for (int j = 0; j < 8; j++) acc[i][j] = 0.0f;

    for (int k0 = 0; k0 < KF; k0 += 16) {
        // load A tile: 128x16 = 512 float4, 2 per thread; store transposed
#pragma unroll
        for (int l = 0; l < 2; l++) {
            int q = tid + l * 256;
            int ar = q >> 2, a4 = q & 3;
            int grow = block_row + ar;
            float4 v = make_float4(0.f, 0.f, 0.f, 0.f);
            if (grow < NN) v = *(const float4*)&A[grow * KF + k0 + a4 * 4];
            As[a4 * 4 + 0][ar] = v.x;
            As[a4 * 4 + 1][ar] = v.y;
            As[a4 * 4 + 2][ar] = v.z;
            As[a4 * 4 + 3][ar] = v.w;
        }
        // load B tile: 16x128 = 512 float4, 2 per thread
#pragma unroll
        for (int l = 0; l < 2; l++) {
            int q = tid + l * 256;
            int br = q >> 5, b4 = q & 31;
            *(float4*)&Bs[br][b4 * 4] = *(const float4*)&B[(k0 + br) * HD + b4 * 4];
        }
        __syncthreads();
#pragma unroll
        for (int kk = 0; kk < 16; kk++) {
            float ra[8], rb[8];
            // two 4-wide slabs (ty*4 and 64+ty*4) -> conflict-free float4 LDS
            float4 va0 = *(const float4*)&As[kk][ty * 4];
            float4 va1 = *(const float4*)&As[kk][64 + ty * 4];
            ra[0] = va0.x; ra[1] = va0.y; ra[2] = va0.z; ra[3] = va0.w;
            ra[4] = va1.x; ra[5] = va1.y; ra[6] = va1.z; ra[7] = va1.w;
            float4 vb0 = *(const float4*)&Bs[kk][tx * 4];
            float4 vb1 = *(const float4*)&Bs[kk][64 + tx * 4];
            rb[0] = vb0.x; rb[1] = vb0.y; rb[2] = vb0.z; rb[3] = vb0.w;
            rb[4] = vb1.x; rb[5] = vb1.y; rb[6] = vb1.z; rb[7] = vb1.w;
#pragma unroll
            for (int i = 0; i < 8; i++)
#pragma unroll
                for (int j = 0; j < 8; j++) acc[i][j] += ra[i] * rb[j];
        }
        __syncthreads();
    }
    // store: rows {ty*4+i, 64+ty*4+i}, cols {tx*4.., 64+tx*4..}
#pragma unroll
    for (int i = 0; i < 8; i++) {
        int grow = block_row + ((i < 4) ? (ty * 4 + i) : (64 + ty * 4 + (i - 4)));
        if (grow < NN) {
            *(float4*)&g_ft[grow * HD + tx * 4] =
                make_float4(acc[i][0], acc[i][1], acc[i][2], acc[i][3]);
            *(float4*)&g_ft[grow * HD + 64 + tx * 4] =
                make_float4(acc[i][4], acc[i][5], acc[i][6], acc[i][7]);
        }
    }
}

// ---------------- per-node logits el/er ----------------
__global__ void el_er_kernel(const float* __restrict__ attn_l,
                             const float* __restrict__ attn_r) {
    int n = blockIdx.x;
    int t = threadIdx.x;          // t = h*32 + d
    float f = g_ft[n * HD + t];
    float l = f * attn_l[t];
    float r = f * attn_r[t];
#pragma unroll
    for (int o = 16; o > 0; o >>= 1) {
        l += __shfl_xor_sync(0xffffffffu, l, o);
        r += __shfl_xor_sync(0xffffffffu, r, o);
    }
    int lane = t & 31;
    int h = t >> 5;
    if (lane == 0) {
        g_el[n * HH + h] = l;
        g_er[n * HH + h] = r;
    }
}

// ---------------- degree histogram ----------------
__global__ void hist_kernel(const int* __restrict__ dst) {
    int e = blockIdx.x * blockDim.x + threadIdx.x;
    if (e < EE) atomicAdd(&g_deg[dst[e]], 1);
}

// ---------------- single-block exclusive scan over deg ----------------
__global__ void scan_kernel() {
    __shared__ int ssum[1024];
    const int CH = (NN + 1023) / 1024;   // 49
    int t = threadIdx.x;
    int base = t * CH;
    int local[CH];
    int sum = 0;
#pragma unroll
    for (int i = 0; i < CH; i++) {
        int idx = base + i;
        int v = (idx < NN) ? g_deg[idx] : 0;
        local[i] = sum;
        sum += v;
    }
    ssum[t] = sum;
    __syncthreads();
    for (int d = 1; d < 1024; d <<= 1) {
        int add = (t >= d) ? ssum[t - d] : 0;
        __syncthreads();
        ssum[t] += add;
        __syncthreads();
    }
    int off = (t == 0) ? 0 : ssum[t - 1];
    for (int i = 0; i < CH; i++) {
        int idx = base + i;
        if (idx < NN) {
            int rs = off + local[i];
            g_rowstart[idx] = rs;
            g_cursor[idx] = rs;
        }
    }
    if (t == 1023) g_rowstart[NN] = off + sum;
}

// ---------------- scatter edge ids into CSR ----------------
__global__ void scatter_kernel(const int* __restrict__ dst) {
    int e = blockIdx.x * blockDim.x + threadIdx.x;
    if (e < EE) {
        int pos = atomicAdd(&g_cursor[dst[e]], 1);
        g_csr[pos] = e;
    }
}

// ---------------- per-edge scores: leaky-relu, exp, segment-sum ----------------
__global__ void edge_kernel(const int* __restrict__ src, const int* __restrict__ dst) {
    int e = blockIdx.x * blockDim.x + threadIdx.x;
    if (e >= EE) return;
    int sn = src[e], dn = dst[e];
    float4 l = *(const float4*)&g_el[sn * HH];
    float4 r = *(const float4*)&g_er[dn * HH];
    float v[4] = {l.x + r.x, l.y + r.y, l.z + r.z, l.w + r.w};
    float ex[4];
#pragma unroll
    for (int h = 0; h < 4; h++) {
        float x = v[h];
        x = (x > 0.f) ? x : 0.2f * x;
        ex[h] = __expf(x);
        atomicAdd(&g_s[dn * HH + h], ex[h]);
    }
    *(float4*)&g_ee[e * HH] = make_float4(ex[0], ex[1], ex[2], ex[3]);
}

// ---------------- SpMM: dst-centric, atomic-free ----------------
__global__ void spmm_kernel(const int* __restrict__ src, float* __restrict__ out,
                            const float* __restrict__ bias) {
    int n = blockIdx.x;
    int h = threadIdx.x >> 5;
    int lane = threadIdx.x & 31;
    int rs = g_rowstart[n], re = g_rowstart[n + 1];
    int off = h * 32 + lane;
    float acc = 0.f;
    for (int base = rs; base < re; base += 32) {
        int cnt = re - base;
        if (cnt > 32) cnt = 32;
        int sn = 0;
        float av = 0.f;
        if (lane < cnt) {
            int eid = g_csr[base + lane];
            sn = src[eid];
            av = g_ee[eid * HH + h];
        }
        for (int j0 = 0; j0 < cnt; j0 += 8) {
#pragma unroll
            for (int jj = 0; jj < 8; jj++) {
                int j = j0 + jj;
                int snj = __shfl_sync(0xffffffffu, sn, j);
                float aj = __shfl_sync(0xffffffffu, av, j);
                acc += g_ft[snj * HD + off] * aj;   // aj==0 past cnt
            }
        }
    }
    float invs = (re > rs) ? (1.0f / g_s[n * HH + h]) : 0.f;
    out[n * HD + off] = acc * invs + bias[off];
}

// ---------------- launch ----------------
extern "C" void kernel_launch(void* const* d_in, const int* in_sizes, int n_in,
                              void* d_out, int out_size) {
    const float* feat   = (const float*)d_in[0];
    const int*   src    = (const int*)  d_in[1];
    const int*   dst    = (const int*)  d_in[2];
    const float* W      = (const float*)d_in[3];
    const float* attn_l = (const float*)d_in[4];
    const float* attn_r = (const float*)d_in[5];
    const float* bias   = (const float*)d_in[6];
    float* out = (float*)d_out;

    init_kernel<<<(NH + 255) / 256, 256>>>();
    gemm_kernel<<<(NN + 127) / 128, 256>>>(feat, W);
    el_er_kernel<<<NN, 128>>>(attn_l, attn_r);
    hist_kernel<<<(EE + 255) / 256, 256>>>(dst);
    scan_kernel<<<1, 1024>>>();
    scatter_kernel<<<(EE + 255) / 256, 256>>>(dst);
    edge_kernel<<<(EE + 255) / 256, 256>>>(src, dst);
    spmm_kernel<<<NN, 128>>>(src, out, bias);
}

// round 4
// speedup vs baseline: 1.2633x; 1.2633x over previous
#include <cuda_runtime.h>
#include <cuda_bf16.h>
#include <cstdint>

#define NN 50000
#define EE 800000
#define KF 256          // IN_FEATS
#define HH 4
#define HD 128          // H*D
#define NH 200000       // N*H
#define MTILE 128
#define KC 64           // K chunk per smem stage
#define NCHUNK (KF / KC)

// ---------------- scratch (device globals; no allocation) ----------------
__device__ float g_ft[NN * HD];
__device__ float g_el[NH];
__device__ float g_er[NH];
__device__ float g_s[NH];
__device__ float g_ee[EE * HH];
__device__ int   g_deg[NN];
__device__ int   g_rowstart[NN + 1];
__device__ int   g_cursor[NN];
__device__ int   g_csr[EE];
__device__ __nv_bfloat16 g_wt_hi[HD * KF];   // W^T split-high  [n][k]
__device__ __nv_bfloat16 g_wt_lo[HD * KF];   // W^T split-low   [n][k]

// ---------------- helpers ----------------
__device__ __forceinline__ uint32_t smem_u32(const void* p) {
    uint32_t a;
    asm("{ .reg .u64 t; cvta.to.shared.u64 t, %1; cvt.u32.u64 %0, t; }" : "=r"(a) : "l"(p));
    return a;
}

#define SW128(o) ((o) ^ (((o) >> 3) & 0x70))

__device__ __forceinline__ void ldm_x4(uint32_t* r, uint32_t addr) {
    asm volatile("ldmatrix.sync.aligned.m8n8.x4.shared.b16 {%0,%1,%2,%3}, [%4];"
                 : "=r"(r[0]), "=r"(r[1]), "=r"(r[2]), "=r"(r[3]) : "r"(addr));
}

__device__ __forceinline__ void mma16816(float* c, const uint32_t* a, const uint32_t* b) {
    asm volatile(
        "mma.sync.aligned.m16n8k16.row.col.f32.bf16.bf16.f32 "
        "{%0,%1,%2,%3}, {%4,%5,%6,%7}, {%8,%9}, {%0,%1,%2,%3};"
        : "+f"(c[0]), "+f"(c[1]), "+f"(c[2]), "+f"(c[3])
        : "r"(a[0]), "r"(a[1]), "r"(a[2]), "r"(a[3]), "r"(b[0]), "r"(b[1]));
}

__device__ __forceinline__ void split_bf16(float x, unsigned short& h, unsigned short& l) {
    __nv_bfloat16 bh = __float2bfloat16(x);
    float r = x - __bfloat162float(bh);
    __nv_bfloat16 bl = __float2bfloat16(r);
    h = __bfloat16_as_ushort(bh);
    l = __bfloat16_as_ushort(bl);
}

// ---------------- init: zero s and deg ----------------
__global__ void init_kernel() {
    int i = blockIdx.x * blockDim.x + threadIdx.x;
    if (i < NH) g_s[i] = 0.0f;
    if (i < NN) g_deg[i] = 0;
}

// ---------------- W transpose + bf16 hi/lo split ----------------
__global__ void wconv_kernel(const float* __restrict__ W) {
    int idx = blockIdx.x * 256 + threadIdx.x;    // 0..32767
    int n = idx >> 8;
    int k = idx & 255;
    float w = W[k * HD + n];
    unsigned short h, l;
    split_bf16(w, h, l);
    g_wt_hi[n * KF + k] = __ushort_as_bfloat16(h);
    g_wt_lo[n * KF + k] = __ushort_as_bfloat16(l);
}

// ---------------- mma.sync bf16x3 GEMM + fused el/er epilogue ----------------
// block: 128 rows x 128 cols, 256 threads = 8 warps (4 m x 2 n), warp = m32 x n64
__global__ void __launch_bounds__(256) gemm_kernel(const float* __restrict__ A,
                                                   const float* __restrict__ attn_l,
                                                   const float* __restrict__ attn_r) {
    extern __shared__ char smem[];
    const uint32_t sbase = smem_u32(smem);
    const uint32_t tiles = (sbase + 1023) & ~1023u;
    const uint32_t tiles_off = tiles - sbase;
    char* tA_hi = smem + tiles_off;
    char* tA_lo = tA_hi + 16384;
    char* tB_hi = tA_lo + 16384;
    char* tB_lo = tB_hi + 16384;
    const uint32_t uA_hi = tiles, uA_lo = tiles + 16384,
                   uB_hi = tiles + 32768, uB_lo = tiles + 49152;

    const int tid = threadIdx.x;
    const int wid = tid >> 5;
    const int lane = tid & 31;
    const int wm = wid & 3;        // warp row group (32 rows)
    const int wn = wid >> 2;       // warp col group (64 cols)
    const int block_row = blockIdx.x * MTILE;

    float acc[2][8][4];            // [m16 tile][n8 tile][frag]
#pragma unroll
    for (int i = 0; i < 2; i++)
#pragma unroll
        for (int j = 0; j < 8; j++)
#pragma unroll
            for (int q = 0; q < 4; q++) acc[i][j][q] = 0.0f;

    // ldmatrix lane->row mapping pieces (constant per thread)
    const int lrow = (lane & 7) + ((lane >> 3) & 1) * 8;  // 0..15
    const int lkh  = (lane >> 4) * 16;                    // 0 or 16 bytes (k+8)

    for (int kc = 0; kc < NCHUNK; kc++) {
        // --- load A chunk [128 x 64] fp32 -> bf16 hi/lo swizzled smem ---
#pragma unroll
        for (int l = 0; l < 8; l++) {
            int q = tid + l * 256;          // 0..2047
            int row = q >> 4;               // 0..127
            int c4 = q & 15;                // float4 within 64-col chunk
            float4 v = make_float4(0.f, 0.f, 0.f, 0.f);
            int grow = block_row + row;
            if (grow < NN) v = *(const float4*)&A[grow * KF + kc * KC + c4 * 4];
            unsigned short h0, h1, h2, h3, l0, l1, l2, l3;
            split_bf16(v.x, h0, l0); split_bf16(v.y, h1, l1);
            split_bf16(v.z, h2, l2); split_bf16(v.w, h3, l3);
            uint32_t off = SW128((uint32_t)(row * 128 + c4 * 8));
            *(uint2*)(tA_hi + off) = make_uint2(((uint32_t)h1 << 16) | h0,
                                                ((uint32_t)h3 << 16) | h2);
            *(uint2*)(tA_lo + off) = make_uint2(((uint32_t)l1 << 16) | l0,
                                                ((uint32_t)l3 << 16) | l2);
        }
        // --- load B chunk [128 n x 64 k] bf16 hi/lo (pre-split W^T), swizzled ---
#pragma unroll
        for (int l = 0; l < 8; l++) {
            int q = tid + l * 256;
            int row = q >> 4;               // n index 0..127
            int c8 = q & 15;                // 8-byte chunk (4 bf16)
            uint2 vh = *(const uint2*)&g_wt_hi[row * KF + kc * KC + c8 * 4];
            uint2 vl = *(const uint2*)&g_wt_lo[row * KF + kc * KC + c8 * 4];
            uint32_t off = SW128((uint32_t)(row * 128 + c8 * 8));
            *(uint2*)(tB_hi + off) = vh;
            *(uint2*)(tB_lo + off) = vl;
        }
        __syncthreads();

#pragma unroll
        for (int ks = 0; ks < 4; ks++) {           // 4 x k16 per chunk
            const int kb = ks * 32;                 // byte offset of k0 in row

            uint32_t ah[2][4], al[2][4];
#pragma unroll
            for (int mt = 0; mt < 2; mt++) {
                int arow = wm * 32 + mt * 16 + lrow;
                uint32_t aoff = SW128((uint32_t)(arow * 128 + kb + lkh));
                ldm_x4(ah[mt], uA_hi + aoff);
                ldm_x4(al[mt], uA_lo + aoff);
            }

#pragma unroll
            for (int np = 0; np < 4; np++) {        // n-tile pairs
                // lanes 0-7: n-tile np*2, k0 ; 8-15: np*2, k8 ; 16-23: np*2+1, k0 ; 24-31: k8
                int brow = wn * 64 + np * 16 + ((lane >> 4) * 8) + (lane & 7);
                uint32_t boff = SW128((uint32_t)(brow * 128 + kb + (((lane >> 3) & 1) * 16)));
                uint32_t bh[4], bl[4];
                ldm_x4(bh, uB_hi + boff);
#pragma unroll
                for (int mt = 0; mt < 2; mt++) {
                    mma16816(acc[mt][np * 2 + 0], ah[mt], bh + 0);
                    mma16816(acc[mt][np * 2 + 1], ah[mt], bh + 2);
                    mma16816(acc[mt][np * 2 + 0], al[mt], bh + 0);
                    mma16816(acc[mt][np * 2 + 1], al[mt], bh + 2);
                }
                ldm_x4(bl, uB_lo + boff);
#pragma unroll
                for (int mt = 0; mt < 2; mt++) {
                    mma16816(acc[mt][np * 2 + 0], ah[mt], bl + 0);
                    mma16816(acc[mt][np * 2 + 1], ah[mt], bl + 2);
                }
            }
        }
        __syncthreads();
    }

    // --- epilogue: store g_ft + fused el/er ---
    const int qrow = lane >> 2;          // 0..7
    const int qcol = (lane & 3) * 2;     // 0,2,4,6
    float elp[4][2], erp[4][2];          // [row slot][head-local]
#pragma unroll
    for (int i = 0; i < 4; i++) { elp[i][0] = elp[i][1] = 0.f; erp[i][0] = erp[i][1] = 0.f; }

#pragma unroll
    for (int nt = 0; nt < 8; nt++) {
        int col = wn * 64 + nt * 8 + qcol;
        int hloc = nt >> 2;
        float wl0 = attn_l[col], wl1 = attn_l[col + 1];
        float wr0 = attn_r[col], wr1 = attn_r[col + 1];
#pragma unroll
        for (int mt = 0; mt < 2; mt++) {
            int r0 = block_row + wm * 32 + mt * 16 + qrow;
            float c0 = acc[mt][nt][0], c1 = acc[mt][nt][1];
            float c2 = acc[mt][nt][2], c3 = acc[mt][nt][3];
            if (r0 < NN) *(float2*)&g_ft[r0 * HD + col] = make_float2(c0, c1);
            if (r0 + 8 < NN) *(float2*)&g_ft[(r0 + 8) * HD + col] = make_float2(c2, c3);
            elp[mt * 2 + 0][hloc] += c0 * wl0 + c1 * wl1;
            erp[mt * 2 + 0][hloc] += c0 * wr0 + c1 * wr1;
            elp[mt * 2 + 1][hloc] += c2 * wl0 + c3 * wl1;
            erp[mt * 2 + 1][hloc] += c2 * wr0 + c3 * wr1;
        }
    }
    // reduce across the 4 lanes sharing a row (lane&3 varies; shfl_xor 1,2 stays in quad)
#pragma unroll
    for (int o = 1; o <= 2; o <<= 1) {
#pragma unroll
        for (int i = 0; i < 4; i++) {
#pragma unroll
            for (int hl = 0; hl < 2; hl++) {
                elp[i][hl] += __shfl_xor_sync(0xffffffffu, elp[i][hl], o);
                erp[i][hl] += __shfl_xor_sync(0xffffffffu, erp[i][hl], o);
            }
        }
    }
    if ((lane & 3) == 0) {
        int hbase = wn * 2;
#pragma unroll
        for (int mt = 0; mt < 2; mt++) {
#pragma unroll
            for (int rh = 0; rh < 2; rh++) {
                int n = block_row + wm * 32 + mt * 16 + qrow + rh * 8;
                if (n < NN) {
                    g_el[n * HH + hbase]     = elp[mt * 2 + rh][0];
                    g_er[n * HH + hbase]     = erp[mt * 2 + rh][0];
                    g_el[n * HH + hbase + 1] = elp[mt * 2 + rh][1];
                    g_er[n * HH + hbase + 1] = erp[mt * 2 + rh][1];
                }
            }
        }
    }
}

// ---------------- degree histogram ----------------
__global__ void hist_kernel(const int* __restrict__ dst) {
    int e = blockIdx.x * blockDim.x + threadIdx.x;
    if (e < EE) atomicAdd(&g_deg[dst[e]], 1);
}

// ---------------- single-block exclusive scan over deg ----------------
__global__ void scan_kernel() {
    __shared__ int ssum[1024];
    const int CH = (NN + 1023) / 1024;   // 49
    int t = threadIdx.x;
    int base = t * CH;
    int local[CH];
    int sum = 0;
#pragma unroll
    for (int i = 0; i < CH; i++) {
        int idx = base + i;
        int v = (idx < NN) ? g_deg[idx] : 0;
        local[i] = sum;
        sum += v;
    }
    ssum[t] = sum;
    __syncthreads();
    for (int d = 1; d < 1024; d <<= 1) {
        int add = (t >= d) ? ssum[t - d] : 0;
        __syncthreads();
        ssum[t] += add;
        __syncthreads();
    }
    int off = (t == 0) ? 0 : ssum[t - 1];
    for (int i = 0; i < CH; i++) {
        int idx = base + i;
        if (idx < NN) {
            int rs = off + local[i];
            g_rowstart[idx] = rs;
            g_cursor[idx] = rs;
        }
    }
    if (t == 1023) g_rowstart[NN] = off + sum;
}

// ---------------- scatter edge ids into CSR ----------------
__global__ void scatter_kernel(const int* __restrict__ dst) {
    int e = blockIdx.x * blockDim.x + threadIdx.x;
    if (e < EE) {
        int pos = atomicAdd(&g_cursor[dst[e]], 1);
        g_csr[pos] = e;
    }
}

// ---------------- per-edge scores: leaky-relu, exp, segment-sum ----------------
__global__ void edge_kernel(const int* __restrict__ src, const int* __restrict__ dst) {
    int e = blockIdx.x * blockDim.x + threadIdx.x;
    if (e >= EE) return;
    int sn = src[e], dn = dst[e];
    float4 l = *(const float4*)&g_el[sn * HH];
    float4 r = *(const float4*)&g_er[dn * HH];
    float v[4] = {l.x + r.x, l.y + r.y, l.z + r.z, l.w + r.w};
    float ex[4];
#pragma unroll
    for (int h = 0; h < 4; h++) {
        float x = v[h];
        x = (x > 0.f) ? x : 0.2f * x;
        ex[h] = __expf(x);
        atomicAdd(&g_s[dn * HH + h], ex[h]);
    }
    *(float4*)&g_ee[e * HH] = make_float4(ex[0], ex[1], ex[2], ex[3]);
}

// ---------------- SpMM: dst-centric, atomic-free ----------------
__global__ void spmm_kernel(const int* __restrict__ src, float* __restrict__ out,
                            const float* __restrict__ bias) {
    int n = blockIdx.x;
    int h = threadIdx.x >> 5;
    int lane = threadIdx.x & 31;
    int rs = g_rowstart[n], re = g_rowstart[n + 1];
    int off = h * 32 + lane;
    float acc = 0.f;
    for (int base = rs; base < re; base += 32) {
        int cnt = re - base;
        if (cnt > 32) cnt = 32;
        int sn = 0;
        float av = 0.f;
        if (lane < cnt) {
            int eid = g_csr[base + lane];
            sn = src[eid];
            av = g_ee[eid * HH + h];
        }
        for (int j0 = 0; j0 < cnt; j0 += 8) {
#pragma unroll
            for (int jj = 0; jj < 8; jj++) {
                int j = j0 + jj;
                int snj = __shfl_sync(0xffffffffu, sn, j);
                float aj = __shfl_sync(0xffffffffu, av, j);
                acc += g_ft[snj * HD + off] * aj;   // aj==0 past cnt
            }
        }
    }
    float invs = (re > rs) ? (1.0f / g_s[n * HH + h]) : 0.f;
    out[n * HD + off] = acc * invs + bias[off];
}

// ---------------- launch ----------------
extern "C" void kernel_launch(void* const* d_in, const int* in_sizes, int n_in,
                              void* d_out, int out_size) {
    const float* feat   = (const float*)d_in[0];
    const int*   src    = (const int*)  d_in[1];
    const int*   dst    = (const int*)  d_in[2];
    const float* W      = (const float*)d_in[3];
    const float* attn_l = (const float*)d_in[4];
    const float* attn_r = (const float*)d_in[5];
    const float* bias   = (const float*)d_in[6];
    float* out = (float*)d_out;

    const int smem_bytes = 4 * 16384 + 1024 + 64;
    cudaFuncSetAttribute(gemm_kernel, cudaFuncAttributeMaxDynamicSharedMemorySize, smem_bytes);

    init_kernel<<<(NH + 255) / 256, 256>>>();
    wconv_kernel<<<(HD * KF) / 256, 256>>>(W);
    gemm_kernel<<<(NN + MTILE - 1) / MTILE, 256, smem_bytes>>>(feat, attn_l, attn_r);
    hist_kernel<<<(EE + 255) / 256, 256>>>(dst);
    scan_kernel<<<1, 1024>>>();
    scatter_kernel<<<(EE + 255) / 256, 256>>>(dst);
    edge_kernel<<<(EE + 255) / 256, 256>>>(src, dst);
    spmm_kernel<<<NN, 128>>>(src, out, bias);
}

// round 7
// speedup vs baseline: 1.4087x; 1.1150x over previous
#include <cuda_runtime.h>
#include <cuda_bf16.h>
#include <cstdint>

#define NN 50000
#define EE 800000
#define KF 256          // IN_FEATS
#define HH 4
#define HD 128          // H*D
#define NH 200000       // N*H
#define MTILE 128
#define KC 64           // K chunk per smem stage
#define NCHUNK (KF / KC)

// ---------------- scratch (device globals; no allocation) ----------------
__device__ float g_ft[NN * HD];
__device__ float g_el[NH];
__device__ float g_er[NH];
__device__ float g_ees[EE * HH];     // exp scores, CSR-sorted by dst
__device__ int   g_srcs[EE];         // src node ids, CSR-sorted by dst
__device__ int   g_deg[NN];
__device__ int   g_rowstart[NN + 1];
__device__ int   g_cursor[NN];
__device__ __nv_bfloat16 g_wt_hi[HD * KF];   // W^T split-high  [n][k]
__device__ __nv_bfloat16 g_wt_lo[HD * KF];   // W^T split-low   [n][k]

// ---------------- helpers ----------------
__device__ __forceinline__ uint32_t smem_u32(const void* p) {
    uint32_t a;
    asm("{ .reg .u64 t; cvta.to.shared.u64 t, %1; cvt.u32.u64 %0, t; }" : "=r"(a) : "l"(p));
    return a;
}

#define SW128(o) ((o) ^ (((o) >> 3) & 0x70))

__device__ __forceinline__ void ldm_x4(uint32_t* r, uint32_t addr) {
    asm volatile("ldmatrix.sync.aligned.m8n8.x4.shared.b16 {%0,%1,%2,%3}, [%4];"
                 : "=r"(r[0]), "=r"(r[1]), "=r"(r[2]), "=r"(r[3]) : "r"(addr));
}

__device__ __forceinline__ void mma16816(float* c, const uint32_t* a, const uint32_t* b) {
    asm volatile(
        "mma.sync.aligned.m16n8k16.row.col.f32.bf16.bf16.f32 "
        "{%0,%1,%2,%3}, {%4,%5,%6,%7}, {%8,%9}, {%0,%1,%2,%3};"
        : "+f"(c[0]), "+f"(c[1]), "+f"(c[2]), "+f"(c[3])
        : "r"(a[0]), "r"(a[1]), "r"(a[2]), "r"(a[3]), "r"(b[0]), "r"(b[1]));
}

__device__ __forceinline__ void split_bf16(float x, unsigned short& h, unsigned short& l) {
    __nv_bfloat16 bh = __float2bfloat16(x);
    float r = x - __bfloat162float(bh);
    __nv_bfloat16 bl = __float2bfloat16(r);
    h = __bfloat16_as_ushort(bh);
    l = __bfloat16_as_ushort(bl);
}

// ---------------- init: zero deg ----------------
__global__ void init_kernel() {
    int i = blockIdx.x * blockDim.x + threadIdx.x;
    if (i < NN) g_deg[i] = 0;
}

// ---------------- W transpose + bf16 hi/lo split ----------------
__global__ void wconv_kernel(const float* __restrict__ W) {
    int idx = blockIdx.x * 256 + threadIdx.x;    // 0..32767
    int n = idx >> 8;
    int k = idx & 255;
    float w = W[k * HD + n];
    unsigned short h, l;
    split_bf16(w, h, l);
    g_wt_hi[n * KF + k] = __ushort_as_bfloat16(h);
    g_wt_lo[n * KF + k] = __ushort_as_bfloat16(l);
}

// ---------------- mma.sync bf16x3 GEMM + fused el/er epilogue ----------------
// block: 128 rows x 128 cols, 256 threads = 8 warps (4 m x 2 n), warp = m32 x n64
__global__ void __launch_bounds__(256) gemm_kernel(const float* __restrict__ A,
                                                   const float* __restrict__ attn_l,
                                                   const float* __restrict__ attn_r) {
    extern __shared__ char smem[];
    const uint32_t sbase = smem_u32(smem);
    const uint32_t tiles = (sbase + 1023) & ~1023u;
    const uint32_t tiles_off = tiles - sbase;
    char* tA_hi = smem + tiles_off;
    char* tA_lo = tA_hi + 16384;
    char* tB_hi = tA_lo + 16384;
    char* tB_lo = tB_hi + 16384;
    const uint32_t uA_hi = tiles, uA_lo = tiles + 16384,
                   uB_hi = tiles + 32768, uB_lo = tiles + 49152;

    const int tid = threadIdx.x;
    const int wid = tid >> 5;
    const int lane = tid & 31;
    const int wm = wid & 3;        // warp row group (32 rows)
    const int wn = wid >> 2;       // warp col group (64 cols)
    const int block_row = blockIdx.x * MTILE;

    float acc[2][8][4];            // [m16 tile][n8 tile][frag]
#pragma unroll
    for (int i = 0; i < 2; i++)
#pragma unroll
        for (int j = 0; j < 8; j++)
#pragma unroll
            for (int q = 0; q < 4; q++) acc[i][j][q] = 0.0f;

    const int lrow = (lane & 7) + ((lane >> 3) & 1) * 8;  // 0..15
    const int lkh  = (lane >> 4) * 16;                    // 0 or 16 bytes (k+8)

    for (int kc = 0; kc < NCHUNK; kc++) {
        // --- load A chunk [128 x 64] fp32 -> bf16 hi/lo swizzled smem ---
#pragma unroll
        for (int l = 0; l < 8; l++) {
            int q = tid + l * 256;          // 0..2047
            int row = q >> 4;               // 0..127
            int c4 = q & 15;                // float4 within 64-col chunk
            float4 v = make_float4(0.f, 0.f, 0.f, 0.f);
            int grow = block_row + row;
            if (grow < NN) v = *(const float4*)&A[grow * KF + kc * KC + c4 * 4];
            unsigned short h0, h1, h2, h3, l0, l1, l2, l3;
            split_bf16(v.x, h0, l0); split_bf16(v.y, h1, l1);
            split_bf16(v.z, h2, l2); split_bf16(v.w, h3, l3);
            uint32_t off = SW128((uint32_t)(row * 128 + c4 * 8));
            *(uint2*)(tA_hi + off) = make_uint2(((uint32_t)h1 << 16) | h0,
                                                ((uint32_t)h3 << 16) | h2);
            *(uint2*)(tA_lo + off) = make_uint2(((uint32_t)l1 << 16) | l0,
                                                ((uint32_t)l3 << 16) | l2);
        }
        // --- load B chunk [128 n x 64 k] bf16 hi/lo (pre-split W^T), swizzled ---
#pragma unroll
        for (int l = 0; l < 8; l++) {
            int q = tid + l * 256;
            int row = q >> 4;               // n index 0..127
            int c8 = q & 15;                // 8-byte chunk (4 bf16)
            uint2 vh = *(const uint2*)&g_wt_hi[row * KF + kc * KC + c8 * 4];
            uint2 vl = *(const uint2*)&g_wt_lo[row * KF + kc * KC + c8 * 4];
            uint32_t off = SW128((uint32_t)(row * 128 + c8 * 8));
            *(uint2*)(tB_hi + off) = vh;
            *(uint2*)(tB_lo + off) = vl;
        }
        __syncthreads();

#pragma unroll
        for (int ks = 0; ks < 4; ks++) {           // 4 x k16 per chunk
            const int kb = ks * 32;                 // byte offset of k0 in row

            uint32_t ah[2][4], al[2][4];
#pragma unroll
            for (int mt = 0; mt < 2; mt++) {
                int arow = wm * 32 + mt * 16 + lrow;
                uint32_t aoff = SW128((uint32_t)(arow * 128 + kb + lkh));
                ldm_x4(ah[mt], uA_hi + aoff);
                ldm_x4(al[mt], uA_lo + aoff);
            }

#pragma unroll
            for (int np = 0; np < 4; np++) {        // n-tile pairs
                int brow = wn * 64 + np * 16 + ((lane >> 4) * 8) + (lane & 7);
                uint32_t boff = SW128((uint32_t)(brow * 128 + kb + (((lane >> 3) & 1) * 16)));
                uint32_t bh[4], bl[4];
                ldm_x4(bh, uB_hi + boff);
#pragma unroll
                for (int mt = 0; mt < 2; mt++) {
                    mma16816(acc[mt][np * 2 + 0], ah[mt], bh + 0);
                    mma16816(acc[mt][np * 2 + 1], ah[mt], bh + 2);
                    mma16816(acc[mt][np * 2 + 0], al[mt], bh + 0);
                    mma16816(acc[mt][np * 2 + 1], al[mt], bh + 2);
                }
                ldm_x4(bl, uB_lo + boff);
#pragma unroll
                for (int mt = 0; mt < 2; mt++) {
                    mma16816(acc[mt][np * 2 + 0], ah[mt], bl + 0);
                    mma16816(acc[mt][np * 2 + 1], ah[mt], bl + 2);
                }
            }
        }
        __syncthreads();
    }

    // --- epilogue: store g_ft + fused el/er ---
    const int qrow = lane >> 2;          // 0..7
    const int qcol = (lane & 3) * 2;     // 0,2,4,6
    float elp[4][2], erp[4][2];
#pragma unroll
    for (int i = 0; i < 4; i++) { elp[i][0] = elp[i][1] = 0.f; erp[i][0] = erp[i][1] = 0.f; }

#pragma unroll
    for (int nt = 0; nt < 8; nt++) {
        int col = wn * 64 + nt * 8 + qcol;
        int hloc = nt >> 2;
        float wl0 = attn_l[col], wl1 = attn_l[col + 1];
        float wr0 = attn_r[col], wr1 = attn_r[col + 1];
#pragma unroll
        for (int mt = 0; mt < 2; mt++) {
            int r0 = block_row + wm * 32 + mt * 16 + qrow;
            float c0 = acc[mt][nt][0], c1 = acc[mt][nt][1];
            float c2 = acc[mt][nt][2], c3 = acc[mt][nt][3];
            if (r0 < NN) *(float2*)&g_ft[r0 * HD + col] = make_float2(c0, c1);
            if (r0 + 8 < NN) *(float2*)&g_ft[(r0 + 8) * HD + col] = make_float2(c2, c3);
            elp[mt * 2 + 0][hloc] += c0 * wl0 + c1 * wl1;
            erp[mt * 2 + 0][hloc] += c0 * wr0 + c1 * wr1;
            elp[mt * 2 + 1][hloc] += c2 * wl0 + c3 * wl1;
            erp[mt * 2 + 1][hloc] += c2 * wr0 + c3 * wr1;
        }
    }
#pragma unroll
    for (int o = 1; o <= 2; o <<= 1) {
#pragma unroll
        for (int i = 0; i < 4; i++) {
#pragma unroll
            for (int hl = 0; hl < 2; hl++) {
                elp[i][hl] += __shfl_xor_sync(0xffffffffu, elp[i][hl], o);
                erp[i][hl] += __shfl_xor_sync(0xffffffffu, erp[i][hl], o);
            }
        }
    }
    if ((lane & 3) == 0) {
        int hbase = wn * 2;
#pragma unroll
        for (int mt = 0; mt < 2; mt++) {
#pragma unroll
            for (int rh = 0; rh < 2; rh++) {
                int n = block_row + wm * 32 + mt * 16 + qrow + rh * 8;
                if (n < NN) {
                    g_el[n * HH + hbase]     = elp[mt * 2 + rh][0];
                    g_er[n * HH + hbase]     = erp[mt * 2 + rh][0];
                    g_el[n * HH + hbase + 1] = elp[mt * 2 + rh][1];
                    g_er[n * HH + hbase + 1] = erp[mt * 2 + rh][1];
                }
            }
        }
    }
}

// ---------------- degree histogram ----------------
__global__ void hist_kernel(const int* __restrict__ dst) {
    int e = blockIdx.x * blockDim.x + threadIdx.x;
    if (e < EE) atomicAdd(&g_deg[dst[e]], 1);
}

// ---------------- single-block exclusive scan over deg ----------------
__global__ void scan_kernel() {
    __shared__ int ssum[1024];
    const int CH = (NN + 1023) / 1024;   // 49
    int t = threadIdx.x;
    int base = t * CH;
    int local[CH];
    int sum = 0;
#pragma unroll
    for (int i = 0; i < CH; i++) {
        int idx = base + i;
        int v = (idx < NN) ? g_deg[idx] : 0;
        local[i] = sum;
        sum += v;
    }
    ssum[t] = sum;
    __syncthreads();
    for (int d = 1; d < 1024; d <<= 1) {
        int add = (t >= d) ? ssum[t - d] : 0;
        __syncthreads();
        ssum[t] += add;
        __syncthreads();
    }
    int off = (t == 0) ? 0 : ssum[t - 1];
    for (int i = 0; i < CH; i++) {
        int idx = base + i;
        if (idx < NN) {
            int rs = off + local[i];
            g_rowstart[idx] = rs;
            g_cursor[idx] = rs;
        }
    }
    if (t == 1023) g_rowstart[NN] = off + sum;
}

// ---------------- fused scatter + edge-softmax-numerator ----------------
// reads src/dst, gathers el/er, computes exp(leaky), writes CSR-sorted payload
__global__ void sced_kernel(const int* __restrict__ src, const int* __restrict__ dst) {
    int e = blockIdx.x * blockDim.x + threadIdx.x;
    if (e >= EE) return;
    int sn = src[e], dn = dst[e];
    float4 l = *(const float4*)&g_el[sn * HH];
    float4 r = *(const float4*)&g_er[dn * HH];
    float v[4] = {l.x + r.x, l.y + r.y, l.z + r.z, l.w + r.w};
    float ex[4];
#pragma unroll
    for (int h = 0; h < 4; h++) {
        float x = v[h];
        x = (x > 0.f) ? x : 0.2f * x;
        ex[h] = __expf(x);
    }
    int pos = atomicAdd(&g_cursor[dn], 1);
    g_srcs[pos] = sn;
    *(float4*)&g_ees[pos * HH] = make_float4(ex[0], ex[1], ex[2], ex[3]);
}

// ---------------- SpMM: dst-centric, atomic-free, inline softmax denom ----------------
__global__ void spmm_kernel(float* __restrict__ out, const float* __restrict__ bias) {
    int n = blockIdx.x;
    int h = threadIdx.x >> 5;
    int lane = threadIdx.x & 31;
    int rs = g_rowstart[n], re = g_rowstart[n + 1];
    int off = h * 32 + lane;
    float acc = 0.f;
    float ssum = 0.f;
    for (int base = rs; base < re; base += 32) {
        int cnt = re - base;
        if (cnt > 32) cnt = 32;
        int sn = 0;
        float av = 0.f;
        if (lane < cnt) {
            sn = g_srcs[base + lane];
            av = g_ees[(base + lane) * HH + h];
        }
        for (int j0 = 0; j0 < cnt; j0 += 8) {
#pragma unroll
            for (int jj = 0; jj < 8; jj++) {
                int j = j0 + jj;
                int snj = __shfl_sync(0xffffffffu, sn, j);
                float aj = __shfl_sync(0xffffffffu, av, j);
                acc += g_ft[snj * HD + off] * aj;   // aj==0 past cnt
                ssum += aj;
            }
        }
    }
    float invs = (re > rs) ? (1.0f / ssum) : 0.f;
    out[n * HD + off] = acc * invs + bias[off];
}

// ---------------- launch ----------------
extern "C" void kernel_launch(void* const* d_in, const int* in_sizes, int n_in,
                              void* d_out, int out_size) {
    const float* feat   = (const float*)d_in[0];
    const int*   src    = (const int*)  d_in[1];
    const int*   dst    = (const int*)  d_in[2];
    const float* W      = (const float*)d_in[3];
    const float* attn_l = (const float*)d_in[4];
    const float* attn_r = (const float*)d_in[5];
    const float* bias   = (const float*)d_in[6];
    float* out = (float*)d_out;

    const int smem_bytes = 4 * 16384 + 1024 + 64;
    cudaFuncSetAttribute(gemm_kernel, cudaFuncAttributeMaxDynamicSharedMemorySize, smem_bytes);

    init_kernel<<<(NN + 255) / 256, 256>>>();
    wconv_kernel<<<(HD * KF) / 256, 256>>>(W);
    hist_kernel<<<(EE + 255) / 256, 256>>>(dst);
    scan_kernel<<<1, 1024>>>();
    gemm_kernel<<<(NN + MTILE - 1) / MTILE, 256, smem_bytes>>>(feat, attn_l, attn_r);
    sced_kernel<<<(EE + 255) / 256, 256>>>(src, dst);
    spmm_kernel<<<NN, 128>>>(out, bias);
}

// round 8
// speedup vs baseline: 1.9106x; 1.3563x over previous
#include <cuda_runtime.h>
#include <cuda_bf16.h>
#include <cstdint>

#define NN 50000
#define EE 800000
#define KF 256          // IN_FEATS
#define HH 4
#define HD 128          // H*D
#define NH 200000       // N*H
#define MTILE 128
#define KC 64           // K chunk per smem stage
#define NCHUNK (KF / KC)
#define NSCB 196        // scan blocks = ceil(NN/256)

// ---------------- scratch (device globals; no allocation) ----------------
__device__ float g_ft[NN * HD];
__device__ float g_el[NH];
__device__ float g_er[NH];
__device__ float g_ees[EE * HH];     // exp scores, CSR-sorted by dst
__device__ int   g_srcs[EE];         // src node ids, CSR-sorted by dst
__device__ int   g_deg[NN];
__device__ int   g_rowstart[NN + 1];
__device__ int   g_cursor[NN];
__device__ int   g_bsum[NSCB];
__device__ int   g_boff[NSCB];
__device__ __nv_bfloat16 g_wt_hi[HD * KF];   // W^T split-high  [n][k]
__device__ __nv_bfloat16 g_wt_lo[HD * KF];   // W^T split-low   [n][k]

// ---------------- helpers ----------------
__device__ __forceinline__ uint32_t smem_u32(const void* p) {
    uint32_t a;
    asm("{ .reg .u64 t; cvta.to.shared.u64 t, %1; cvt.u32.u64 %0, t; }" : "=r"(a) : "l"(p));
    return a;
}

#define SW128(o) ((o) ^ (((o) >> 3) & 0x70))

__device__ __forceinline__ void ldm_x4(uint32_t* r, uint32_t addr) {
    asm volatile("ldmatrix.sync.aligned.m8n8.x4.shared.b16 {%0,%1,%2,%3}, [%4];"
                 : "=r"(r[0]), "=r"(r[1]), "=r"(r[2]), "=r"(r[3]) : "r"(addr));
}

__device__ __forceinline__ void mma16816(float* c, const uint32_t* a, const uint32_t* b) {
    asm volatile(
        "mma.sync.aligned.m16n8k16.row.col.f32.bf16.bf16.f32 "
        "{%0,%1,%2,%3}, {%4,%5,%6,%7}, {%8,%9}, {%0,%1,%2,%3};"
        : "+f"(c[0]), "+f"(c[1]), "+f"(c[2]), "+f"(c[3])
        : "r"(a[0]), "r"(a[1]), "r"(a[2]), "r"(a[3]), "r"(b[0]), "r"(b[1]));
}

__device__ __forceinline__ void split_bf16(float x, unsigned short& h, unsigned short& l) {
    __nv_bfloat16 bh = __float2bfloat16(x);
    float r = x - __bfloat162float(bh);
    __nv_bfloat16 bl = __float2bfloat16(r);
    h = __bfloat16_as_ushort(bh);
    l = __bfloat16_as_ushort(bl);
}

// ---------------- init: zero deg ----------------
__global__ void init_kernel() {
    int i = blockIdx.x * blockDim.x + threadIdx.x;
    if (i < NN) g_deg[i] = 0;
}

// ---------------- W transpose + bf16 hi/lo split ----------------
__global__ void wconv_kernel(const float* __restrict__ W) {
    int idx = blockIdx.x * 256 + threadIdx.x;    // 0..32767
    int n = idx >> 8;
    int k = idx & 255;
    float w = W[k * HD + n];
    unsigned short h, l;
    split_bf16(w, h, l);
    g_wt_hi[n * KF + k] = __ushort_as_bfloat16(h);
    g_wt_lo[n * KF + k] = __ushort_as_bfloat16(l);
}

// ---------------- mma.sync bf16x3 GEMM + fused el/er epilogue ----------------
__global__ void __launch_bounds__(256) gemm_kernel(const float* __restrict__ A,
                                                   const float* __restrict__ attn_l,
                                                   const float* __restrict__ attn_r) {
    extern __shared__ char smem[];
    const uint32_t sbase = smem_u32(smem);
    const uint32_t tiles = (sbase + 1023) & ~1023u;
    const uint32_t tiles_off = tiles - sbase;
    char* tA_hi = smem + tiles_off;
    char* tA_lo = tA_hi + 16384;
    char* tB_hi = tA_lo + 16384;
    char* tB_lo = tB_hi + 16384;
    const uint32_t uA_hi = tiles, uA_lo = tiles + 16384,
                   uB_hi = tiles + 32768, uB_lo = tiles + 49152;

    const int tid = threadIdx.x;
    const int wid = tid >> 5;
    const int lane = tid & 31;
    const int wm = wid & 3;
    const int wn = wid >> 2;
    const int block_row = blockIdx.x * MTILE;

    float acc[2][8][4];
#pragma unroll
    for (int i = 0; i < 2; i++)
#pragma unroll
        for (int j = 0; j < 8; j++)
#pragma unroll
            for (int q = 0; q < 4; q++) acc[i][j][q] = 0.0f;

    const int lrow = (lane & 7) + ((lane >> 3) & 1) * 8;
    const int lkh  = (lane >> 4) * 16;

    for (int kc = 0; kc < NCHUNK; kc++) {
#pragma unroll
        for (int l = 0; l < 8; l++) {
            int q = tid + l * 256;
            int row = q >> 4;
            int c4 = q & 15;
            float4 v = make_float4(0.f, 0.f, 0.f, 0.f);
            int grow = block_row + row;
            if (grow < NN) v = *(const float4*)&A[grow * KF + kc * KC + c4 * 4];
            unsigned short h0, h1, h2, h3, l0, l1, l2, l3;
            split_bf16(v.x, h0, l0); split_bf16(v.y, h1, l1);
            split_bf16(v.z, h2, l2); split_bf16(v.w, h3, l3);
            uint32_t off = SW128((uint32_t)(row * 128 + c4 * 8));
            *(uint2*)(tA_hi + off) = make_uint2(((uint32_t)h1 << 16) | h0,
                                                ((uint32_t)h3 << 16) | h2);
            *(uint2*)(tA_lo + off) = make_uint2(((uint32_t)l1 << 16) | l0,
                                                ((uint32_t)l3 << 16) | l2);
        }
#pragma unroll
        for (int l = 0; l < 8; l++) {
            int q = tid + l * 256;
            int row = q >> 4;
            int c8 = q & 15;
            uint2 vh = *(const uint2*)&g_wt_hi[row * KF + kc * KC + c8 * 4];
            uint2 vl = *(const uint2*)&g_wt_lo[row * KF + kc * KC + c8 * 4];
            uint32_t off = SW128((uint32_t)(row * 128 + c8 * 8));
            *(uint2*)(tB_hi + off) = vh;
            *(uint2*)(tB_lo + off) = vl;
        }
        __syncthreads();

#pragma unroll
        for (int ks = 0; ks < 4; ks++) {
            const int kb = ks * 32;

            uint32_t ah[2][4], al[2][4];
#pragma unroll
            for (int mt = 0; mt < 2; mt++) {
                int arow = wm * 32 + mt * 16 + lrow;
                uint32_t aoff = SW128((uint32_t)(arow * 128 + kb + lkh));
                ldm_x4(ah[mt], uA_hi + aoff);
                ldm_x4(al[mt], uA_lo + aoff);
            }

#pragma unroll
            for (int np = 0; np < 4; np++) {
                int brow = wn * 64 + np * 16 + ((lane >> 4) * 8) + (lane & 7);
                uint32_t boff = SW128((uint32_t)(brow * 128 + kb + (((lane >> 3) & 1) * 16)));
                uint32_t bh[4], bl[4];
                ldm_x4(bh, uB_hi + boff);
#pragma unroll
                for (int mt = 0; mt < 2; mt++) {
                    mma16816(acc[mt][np * 2 + 0], ah[mt], bh + 0);
                    mma16816(acc[mt][np * 2 + 1], ah[mt], bh + 2);
                    mma16816(acc[mt][np * 2 + 0], al[mt], bh + 0);
                    mma16816(acc[mt][np * 2 + 1], al[mt], bh + 2);
                }
                ldm_x4(bl, uB_lo + boff);
#pragma unroll
                for (int mt = 0; mt < 2; mt++) {
                    mma16816(acc[mt][np * 2 + 0], ah[mt], bl + 0);
                    mma16816(acc[mt][np * 2 + 1], ah[mt], bl + 2);
                }
            }
        }
        __syncthreads();
    }

    // --- epilogue: store g_ft + fused el/er ---
    const int qrow = lane >> 2;
    const int qcol = (lane & 3) * 2;
    float elp[4][2], erp[4][2];
#pragma unroll
    for (int i = 0; i < 4; i++) { elp[i][0] = elp[i][1] = 0.f; erp[i][0] = erp[i][1] = 0.f; }

#pragma unroll
    for (int nt = 0; nt < 8; nt++) {
        int col = wn * 64 + nt * 8 + qcol;
        int hloc = nt >> 2;
        float wl0 = attn_l[col], wl1 = attn_l[col + 1];
        float wr0 = attn_r[col], wr1 = attn_r[col + 1];
#pragma unroll
        for (int mt = 0; mt < 2; mt++) {
            int r0 = block_row + wm * 32 + mt * 16 + qrow;
            float c0 = acc[mt][nt][0], c1 = acc[mt][nt][1];
            float c2 = acc[mt][nt][2], c3 = acc[mt][nt][3];
            if (r0 < NN) *(float2*)&g_ft[r0 * HD + col] = make_float2(c0, c1);
            if (r0 + 8 < NN) *(float2*)&g_ft[(r0 + 8) * HD + col] = make_float2(c2, c3);
            elp[mt * 2 + 0][hloc] += c0 * wl0 + c1 * wl1;
            erp[mt * 2 + 0][hloc] += c0 * wr0 + c1 * wr1;
            elp[mt * 2 + 1][hloc] += c2 * wl0 + c3 * wl1;
            erp[mt * 2 + 1][hloc] += c2 * wr0 + c3 * wr1;
        }
    }
#pragma unroll
    for (int o = 1; o <= 2; o <<= 1) {
#pragma unroll
        for (int i = 0; i < 4; i++) {
#pragma unroll
            for (int hl = 0; hl < 2; hl++) {
                elp[i][hl] += __shfl_xor_sync(0xffffffffu, elp[i][hl], o);
                erp[i][hl] += __shfl_xor_sync(0xffffffffu, erp[i][hl], o);
            }
        }
    }
    if ((lane & 3) == 0) {
        int hbase = wn * 2;
#pragma unroll
        for (int mt = 0; mt < 2; mt++) {
#pragma unroll
            for (int rh = 0; rh < 2; rh++) {
                int n = block_row + wm * 32 + mt * 16 + qrow + rh * 8;
                if (n < NN) {
                    g_el[n * HH + hbase]     = elp[mt * 2 + rh][0];
                    g_er[n * HH + hbase]     = erp[mt * 2 + rh][0];
                    g_el[n * HH + hbase + 1] = elp[mt * 2 + rh][1];
                    g_er[n * HH + hbase + 1] = erp[mt * 2 + rh][1];
                }
            }
        }
    }
}

// ---------------- degree histogram ----------------
__global__ void hist_kernel(const int* __restrict__ dst) {
    int e = blockIdx.x * blockDim.x + threadIdx.x;
    if (e < EE) atomicAdd(&g_deg[dst[e]], 1);
}

// ---------------- hierarchical scan: 3 small wide kernels ----------------
__global__ void scan1_kernel() {
    __shared__ int sh[256];
    int t = threadIdx.x;
    int idx = blockIdx.x * 256 + t;
    int v = (idx < NN) ? g_deg[idx] : 0;
    sh[t] = v;
    __syncthreads();
#pragma unroll
    for (int d = 1; d < 256; d <<= 1) {
        int a = (t >= d) ? sh[t - d] : 0;
        __syncthreads();
        sh[t] += a;
        __syncthreads();
    }
    if (idx < NN) g_rowstart[idx] = sh[t] - v;          // exclusive within block
    if (t == 255) g_bsum[blockIdx.x] = sh[255];
}

__global__ void scan2_kernel() {
    __shared__ int sh[256];
    int t = threadIdx.x;
    int v = (t < NSCB) ? g_bsum[t] : 0;
    sh[t] = v;
    __syncthreads();
#pragma unroll
    for (int d = 1; d < 256; d <<= 1) {
        int a = (t >= d) ? sh[t - d] : 0;
        __syncthreads();
        sh[t] += a;
        __syncthreads();
    }
    if (t < NSCB) g_boff[t] = sh[t] - v;                // exclusive block offsets
}

__global__ void scan3_kernel() {
    int idx = blockIdx.x * 256 + threadIdx.x;
    if (idx < NN) {
        int rs = g_rowstart[idx] + g_boff[blockIdx.x];
        g_rowstart[idx] = rs;
        g_cursor[idx] = rs;
    }
    if (idx == 0) g_rowstart[NN] = EE;                  // all edges counted
}

// ---------------- fused scatter + edge-softmax-numerator ----------------
__global__ void sced_kernel(const int* __restrict__ src, const int* __restrict__ dst) {
    int e = blockIdx.x * blockDim.x + threadIdx.x;
    if (e >= EE) return;
    int sn = src[e], dn = dst[e];
    float4 l = *(const float4*)&g_el[sn * HH];
    float4 r = *(const float4*)&g_er[dn * HH];
    float v[4] = {l.x + r.x, l.y + r.y, l.z + r.z, l.w + r.w};
    float ex[4];
#pragma unroll
    for (int h = 0; h < 4; h++) {
        float x = v[h];
        x = (x > 0.f) ? x : 0.2f * x;
        ex[h] = __expf(x);
    }
    int pos = atomicAdd(&g_cursor[dn], 1);
    g_srcs[pos] = sn;
    *(float4*)&g_ees[pos * HH] = make_float4(ex[0], ex[1], ex[2], ex[3]);
}

// ---------------- SpMM: dst-centric, atomic-free, inline softmax denom ----------------
__global__ void spmm_kernel(float* __restrict__ out, const float* __restrict__ bias) {
    int n = blockIdx.x;
    int h = threadIdx.x >> 5;
    int lane = threadIdx.x & 31;
    int rs = g_rowstart[n], re = g_rowstart[n + 1];
    int off = h * 32 + lane;
    float acc = 0.f;
    float ssum = 0.f;
    for (int base = rs; base < re; base += 32) {
        int cnt = re - base;
        if (cnt > 32) cnt = 32;
        int sn = 0;
        float av = 0.f;
        if (lane < cnt) {
            sn = g_srcs[base + lane];
            av = g_ees[(base + lane) * HH + h];
        }
        for (int j0 = 0; j0 < cnt; j0 += 8) {
#pragma unroll
            for (int jj = 0; jj < 8; jj++) {
                int j = j0 + jj;
                int snj = __shfl_sync(0xffffffffu, sn, j);
                float aj = __shfl_sync(0xffffffffu, av, j);
                acc += g_ft[snj * HD + off] * aj;   // aj==0 past cnt
                ssum += aj;
            }
        }
    }
    float invs = (re > rs) ? (1.0f / ssum) : 0.f;
    out[n * HD + off] = acc * invs + bias[off];
}

// ---------------- launch ----------------
extern "C" void kernel_launch(void* const* d_in, const int* in_sizes, int n_in,
                              void* d_out, int out_size) {
    const float* feat   = (const float*)d_in[0];
    const int*   src    = (const int*)  d_in[1];
    const int*   dst    = (const int*)  d_in[2];
    const float* W      = (const float*)d_in[3];
    const float* attn_l = (const float*)d_in[4];
    const float* attn_r = (const float*)d_in[5];
    const float* bias   = (const float*)d_in[6];
    float* out = (float*)d_out;

    const int smem_bytes = 4 * 16384 + 1024 + 64;
    cudaFuncSetAttribute(gemm_kernel, cudaFuncAttributeMaxDynamicSharedMemorySize, smem_bytes);

    init_kernel<<<(NN + 255) / 256, 256>>>();
    wconv_kernel<<<(HD * KF) / 256, 256>>>(W);
    hist_kernel<<<(EE + 255) / 256, 256>>>(dst);
    scan1_kernel<<<NSCB, 256>>>();
    scan2_kernel<<<1, 256>>>();
    scan3_kernel<<<NSCB, 256>>>();
    gemm_kernel<<<(NN + MTILE - 1) / MTILE, 256, smem_bytes>>>(feat, attn_l, attn_r);
    sced_kernel<<<(EE + 255) / 256, 256>>>(src, dst);
    spmm_kernel<<<NN, 128>>>(out, bias);
}

// round 9
// speedup vs baseline: 1.9362x; 1.0134x over previous
#include <cuda_runtime.h>
#include <cuda_bf16.h>
#include <cstdint>

#define NN 50000
#define EE 800000
#define KF 256          // IN_FEATS
#define HH 4
#define HD 128          // H*D
#define NH 200000       // N*H
#define MTILE 128
#define KC 64           // K chunk per smem stage
#define NCHUNK (KF / KC)
#define NSCB 196        // scan blocks = ceil(NN/256)
#define STG_BYTES 65536 // 4 tiles x 16KB per pipeline stage

// ---------------- scratch (device globals; no allocation) ----------------
__device__ float g_ft[NN * HD];
__device__ float g_el[NH];
__device__ float g_er[NH];
__device__ float g_ees[EE * HH];     // exp scores, CSR-sorted by dst
__device__ int   g_srcs[EE];         // src node ids, CSR-sorted by dst
__device__ int   g_deg[NN];
__device__ int   g_rank[EE];         // rank of edge within its dst segment
__device__ int   g_rowstart[NN + 1];
__device__ int   g_bsum[NSCB];
__device__ int   g_boff[NSCB];
__device__ __nv_bfloat16 g_a_hi[NN * KF];    // feat split-high
__device__ __nv_bfloat16 g_a_lo[NN * KF];    // feat split-low
__device__ __nv_bfloat16 g_wt_hi[HD * KF];   // W^T split-high  [n][k]
__device__ __nv_bfloat16 g_wt_lo[HD * KF];   // W^T split-low   [n][k]

// ---------------- helpers ----------------
__device__ __forceinline__ uint32_t smem_u32(const void* p) {
    uint32_t a;
    asm("{ .reg .u64 t; cvta.to.shared.u64 t, %1; cvt.u32.u64 %0, t; }" : "=r"(a) : "l"(p));
    return a;
}

#define SW128(o) ((o) ^ (((o) >> 3) & 0x70))

__device__ __forceinline__ void ldm_x4(uint32_t* r, uint32_t addr) {
    asm volatile("ldmatrix.sync.aligned.m8n8.x4.shared.b16 {%0,%1,%2,%3}, [%4];"
                 : "=r"(r[0]), "=r"(r[1]), "=r"(r[2]), "=r"(r[3]) : "r"(addr));
}

__device__ __forceinline__ void mma16816(float* c, const uint32_t* a, const uint32_t* b) {
    asm volatile(
        "mma.sync.aligned.m16n8k16.row.col.f32.bf16.bf16.f32 "
        "{%0,%1,%2,%3}, {%4,%5,%6,%7}, {%8,%9}, {%0,%1,%2,%3};"
        : "+f"(c[0]), "+f"(c[1]), "+f"(c[2]), "+f"(c[3])
        : "r"(a[0]), "r"(a[1]), "r"(a[2]), "r"(a[3]), "r"(b[0]), "r"(b[1]));
}

__device__ __forceinline__ void split_bf16(float x, unsigned short& h, unsigned short& l) {
    __nv_bfloat16 bh = __float2bfloat16(x);
    float r = x - __bfloat162float(bh);
    __nv_bfloat16 bl = __float2bfloat16(r);
    h = __bfloat16_as_ushort(bh);
    l = __bfloat16_as_ushort(bl);
}

// ---------------- init: zero deg ----------------
__global__ void init_kernel() {
    int i = blockIdx.x * blockDim.x + threadIdx.x;
    if (i < NN) g_deg[i] = 0;
}

// ---------------- feat -> bf16 hi/lo split (one pass) ----------------
__global__ void afconv_kernel(const float* __restrict__ feat) {
    int i = blockIdx.x * 256 + threadIdx.x;      // float4 index
    if (i < NN * KF / 4) {
        float4 v = ((const float4*)feat)[i];
        unsigned short h0, h1, h2, h3, l0, l1, l2, l3;
        split_bf16(v.x, h0, l0); split_bf16(v.y, h1, l1);
        split_bf16(v.z, h2, l2); split_bf16(v.w, h3, l3);
        ((uint2*)g_a_hi)[i] = make_uint2(((uint32_t)h1 << 16) | h0,
                                         ((uint32_t)h3 << 16) | h2);
        ((uint2*)g_a_lo)[i] = make_uint2(((uint32_t)l1 << 16) | l0,
                                         ((uint32_t)l3 << 16) | l2);
    }
}

// ---------------- W transpose + bf16 hi/lo split ----------------
__global__ void wconv_kernel(const float* __restrict__ W) {
    int idx = blockIdx.x * 256 + threadIdx.x;    // 0..32767
    int n = idx >> 8;
    int k = idx & 255;
    float w = W[k * HD + n];
    unsigned short h, l;
    split_bf16(w, h, l);
    g_wt_hi[n * KF + k] = __ushort_as_bfloat16(h);
    g_wt_lo[n * KF + k] = __ushort_as_bfloat16(l);
}

// ---------------- cp.async stage fill ----------------
__device__ __forceinline__ void issue_tiles(int block_row, int kc, uint32_t stg, int tid) {
    // A tiles (hi/lo): 128 rows x 128B, 16B per cp
#pragma unroll
    for (int l = 0; l < 4; l++) {
        int q = tid + l * 256;          // 0..1023
        int row = q >> 3, c = q & 7;
        int grow = block_row + row;
        int ok = (grow < NN) ? 16 : 0;
        int gidx = (grow < NN ? grow : NN - 1) * KF + kc * KC + c * 8;
        uint32_t off = SW128((uint32_t)(row * 128 + c * 16));
        asm volatile("cp.async.cg.shared.global [%0], [%1], 16, %2;"
                     :: "r"(stg + off), "l"(&g_a_hi[gidx]), "r"(ok));
        asm volatile("cp.async.cg.shared.global [%0], [%1], 16, %2;"
                     :: "r"(stg + 16384 + off), "l"(&g_a_lo[gidx]), "r"(ok));
    }
    // B tiles (hi/lo)
#pragma unroll
    for (int l = 0; l < 4; l++) {
        int q = tid + l * 256;
        int row = q >> 3, c = q & 7;
        int gidx = row * KF + kc * KC + c * 8;
        uint32_t off = SW128((uint32_t)(row * 128 + c * 16));
        asm volatile("cp.async.cg.shared.global [%0], [%1], 16, %2;"
                     :: "r"(stg + 32768 + off), "l"(&g_wt_hi[gidx]), "r"(16));
        asm volatile("cp.async.cg.shared.global [%0], [%1], 16, %2;"
                     :: "r"(stg + 49152 + off), "l"(&g_wt_lo[gidx]), "r"(16));
    }
    asm volatile("cp.async.commit_group;" ::: "memory");
}

// ---------------- mma.sync bf16x3 GEMM, 2-stage cp.async pipeline ----------------
__global__ void __launch_bounds__(256) gemm_kernel(const float* __restrict__ attn_l,
                                                   const float* __restrict__ attn_r) {
    extern __shared__ char smem[];
    const uint32_t sbase = smem_u32(smem);
    const uint32_t tiles = (sbase + 1023) & ~1023u;
    const uint32_t stg0 = tiles, stg1 = tiles + STG_BYTES;

    const int tid = threadIdx.x;
    const int wid = tid >> 5;
    const int lane = tid & 31;
    const int wm = wid & 3;
    const int wn = wid >> 2;
    const int block_row = blockIdx.x * MTILE;

    float acc[2][8][4];
#pragma unroll
    for (int i = 0; i < 2; i++)
#pragma unroll
        for (int j = 0; j < 8; j++)
#pragma unroll
            for (int q = 0; q < 4; q++) acc[i][j][q] = 0.0f;

    const int lrow = (lane & 7) + ((lane >> 3) & 1) * 8;
    const int lkh  = (lane >> 4) * 16;

    issue_tiles(block_row, 0, stg0, tid);

    for (int kc = 0; kc < NCHUNK; kc++) {
        const uint32_t cur = (kc & 1) ? stg1 : stg0;
        if (kc + 1 < NCHUNK) {
            issue_tiles(block_row, kc + 1, (kc & 1) ? stg0 : stg1, tid);
            asm volatile("cp.async.wait_group 1;" ::: "memory");
        } else {
            asm volatile("cp.async.wait_group 0;" ::: "memory");
        }
        __syncthreads();

        const uint32_t uA_hi = cur, uA_lo = cur + 16384,
                       uB_hi = cur + 32768, uB_lo = cur + 49152;
#pragma unroll
        for (int ks = 0; ks < 4; ks++) {
            const int kb = ks * 32;

            uint32_t ah[2][4], al[2][4];
#pragma unroll
            for (int mt = 0; mt < 2; mt++) {
                int arow = wm * 32 + mt * 16 + lrow;
                uint32_t aoff = SW128((uint32_t)(arow * 128 + kb + lkh));
                ldm_x4(ah[mt], uA_hi + aoff);
                ldm_x4(al[mt], uA_lo + aoff);
            }

#pragma unroll
            for (int np = 0; np < 4; np++) {
                int brow = wn * 64 + np * 16 + ((lane >> 4) * 8) + (lane & 7);
                uint32_t boff = SW128((uint32_t)(brow * 128 + kb + (((lane >> 3) & 1) * 16)));
                uint32_t bh[4], bl[4];
                ldm_x4(bh, uB_hi + boff);
#pragma unroll
                for (int mt = 0; mt < 2; mt++) {
                    mma16816(acc[mt][np * 2 + 0], ah[mt], bh + 0);
                    mma16816(acc[mt][np * 2 + 1], ah[mt], bh + 2);
                    mma16816(acc[mt][np * 2 + 0], al[mt], bh + 0);
                    mma16816(acc[mt][np * 2 + 1], al[mt], bh + 2);
                }
                ldm_x4(bl, uB_lo + boff);
#pragma unroll
                for (int mt = 0; mt < 2; mt++) {
                    mma16816(acc[mt][np * 2 + 0], ah[mt], bl + 0);
                    mma16816(acc[mt][np * 2 + 1], ah[mt], bl + 2);
                }
            }
        }
        __syncthreads();
    }

    // --- epilogue: store g_ft + fused el/er ---
    const int qrow = lane >> 2;
    const int qcol = (lane & 3) * 2;
    float elp[4][2], erp[4][2];
#pragma unroll
    for (int i = 0; i < 4; i++) { elp[i][0] = elp[i][1] = 0.f; erp[i][0] = erp[i][1] = 0.f; }

#pragma unroll
    for (int nt = 0; nt < 8; nt++) {
        int col = wn * 64 + nt * 8 + qcol;
        int hloc = nt >> 2;
        float wl0 = attn_l[col], wl1 = attn_l[col + 1];
        float wr0 = attn_r[col], wr1 = attn_r[col + 1];
#pragma unroll
        for (int mt = 0; mt < 2; mt++) {
            int r0 = block_row + wm * 32 + mt * 16 + qrow;
            float c0 = acc[mt][nt][0], c1 = acc[mt][nt][1];
            float c2 = acc[mt][nt][2], c3 = acc[mt][nt][3];
            if (r0 < NN) *(float2*)&g_ft[r0 * HD + col] = make_float2(c0, c1);
            if (r0 + 8 < NN) *(float2*)&g_ft[(r0 + 8) * HD + col] = make_float2(c2, c3);
            elp[mt * 2 + 0][hloc] += c0 * wl0 + c1 * wl1;
            erp[mt * 2 + 0][hloc] += c0 * wr0 + c1 * wr1;
            elp[mt * 2 + 1][hloc] += c2 * wl0 + c3 * wl1;
            erp[mt * 2 + 1][hloc] += c2 * wr0 + c3 * wr1;
        }
    }
#pragma unroll
    for (int o = 1; o <= 2; o <<= 1) {
#pragma unroll
        for (int i = 0; i < 4; i++) {
#pragma unroll
            for (int hl = 0; hl < 2; hl++) {
                elp[i][hl] += __shfl_xor_sync(0xffffffffu, elp[i][hl], o);
                erp[i][hl] += __shfl_xor_sync(0xffffffffu, erp[i][hl], o);
            }
        }
    }
    if ((lane & 3) == 0) {
        int hbase = wn * 2;
#pragma unroll
        for (int mt = 0; mt < 2; mt++) {
#pragma unroll
            for (int rh = 0; rh < 2; rh++) {
                int n = block_row + wm * 32 + mt * 16 + qrow + rh * 8;
                if (n < NN) {
                    g_el[n * HH + hbase]     = elp[mt * 2 + rh][0];
                    g_er[n * HH + hbase]     = erp[mt * 2 + rh][0];
                    g_el[n * HH + hbase + 1] = elp[mt * 2 + rh][1];
                    g_er[n * HH + hbase + 1] = erp[mt * 2 + rh][1];
                }
            }
        }
    }
}

// ---------------- degree histogram (keeps per-edge rank) ----------------
__global__ void hist_kernel(const int* __restrict__ dst) {
    int e = blockIdx.x * blockDim.x + threadIdx.x;
    if (e < EE) g_rank[e] = atomicAdd(&g_deg[dst[e]], 1);
}

// ---------------- hierarchical scan: 3 small wide kernels ----------------
__global__ void scan1_kernel() {
    __shared__ int sh[256];
    int t = threadIdx.x;
    int idx = blockIdx.x * 256 + t;
    int v = (idx < NN) ? g_deg[idx] : 0;
    sh[t] = v;
    __syncthreads();
#pragma unroll
    for (int d = 1; d < 256; d <<= 1) {
        int a = (t >= d) ? sh[t - d] : 0;
        __syncthreads();
        sh[t] += a;
        __syncthreads();
    }
    if (idx < NN) g_rowstart[idx] = sh[t] - v;
    if (t == 255) g_bsum[blockIdx.x] = sh[255];
}

__global__ void scan2_kernel() {
    __shared__ int sh[256];
    int t = threadIdx.x;
    int v = (t < NSCB) ? g_bsum[t] : 0;
    sh[t] = v;
    __syncthreads();
#pragma unroll
    for (int d = 1; d < 256; d <<= 1) {
        int a = (t >= d) ? sh[t - d] : 0;
        __syncthreads();
        sh[t] += a;
        __syncthreads();
    }
    if (t < NSCB) g_boff[t] = sh[t] - v;
}

__global__ void scan3_kernel() {
    int idx = blockIdx.x * 256 + threadIdx.x;
    if (idx < NN) g_rowstart[idx] += g_boff[blockIdx.x];
    if (idx == 0) g_rowstart[NN] = EE;
}

// ---------------- fused scatter + edge-softmax-numerator (atomic-free) ----------------
__global__ void sced_kernel(const int* __restrict__ src, const int* __restrict__ dst) {
    int e = blockIdx.x * blockDim.x + threadIdx.x;
    if (e >= EE) return;
    int sn = src[e], dn = dst[e];
    float4 l = *(const float4*)&g_el[sn * HH];
    float4 r = *(const float4*)&g_er[dn * HH];
    float v[4] = {l.x + r.x, l.y + r.y, l.z + r.z, l.w + r.w};
    float ex[4];
#pragma unroll
    for (int h = 0; h < 4; h++) {
        float x = v[h];
        x = (x > 0.f) ? x : 0.2f * x;
        ex[h] = __expf(x);
    }
    int pos = g_rowstart[dn] + g_rank[e];
    g_srcs[pos] = sn;
    *(float4*)&g_ees[pos * HH] = make_float4(ex[0], ex[1], ex[2], ex[3]);
}

// ---------------- SpMM: dst-centric, atomic-free, inline softmax denom ----------------
__global__ void spmm_kernel(float* __restrict__ out, const float* __restrict__ bias) {
    int n = blockIdx.x;
    int h = threadIdx.x >> 5;
    int lane = threadIdx.x & 31;
    int rs = g_rowstart[n], re = g_rowstart[n + 1];
    int off = h * 32 + lane;
    float acc = 0.f;
    float ssum = 0.f;
    for (int base = rs; base < re; base += 32) {
        int cnt = re - base;
        if (cnt > 32) cnt = 32;
        int sn = 0;
        float av = 0.f;
        if (lane < cnt) {
            sn = g_srcs[base + lane];
            av = g_ees[(base + lane) * HH + h];
        }
        for (int j0 = 0; j0 < cnt; j0 += 8) {
#pragma unroll
            for (int jj = 0; jj < 8; jj++) {
                int j = j0 + jj;
                int snj = __shfl_sync(0xffffffffu, sn, j);
                float aj = __shfl_sync(0xffffffffu, av, j);
                acc += g_ft[snj * HD + off] * aj;   // aj==0 past cnt
                ssum += aj;
            }
        }
    }
    float invs = (re > rs) ? (1.0f / ssum) : 0.f;
    out[n * HD + off] = acc * invs + bias[off];
}

// ---------------- launch ----------------
extern "C" void kernel_launch(void* const* d_in, const int* in_sizes, int n_in,
                              void* d_out, int out_size) {
    const float* feat   = (const float*)d_in[0];
    const int*   src    = (const int*)  d_in[1];
    const int*   dst    = (const int*)  d_in[2];
    const float* W      = (const float*)d_in[3];
    const float* attn_l = (const float*)d_in[4];
    const float* attn_r = (const float*)d_in[5];
    const float* bias   = (const float*)d_in[6];
    float* out = (float*)d_out;

    const int smem_bytes = 2 * STG_BYTES + 1024 + 64;
    cudaFuncSetAttribute(gemm_kernel, cudaFuncAttributeMaxDynamicSharedMemorySize, smem_bytes);

    init_kernel<<<(NN + 255) / 256, 256>>>();
    afconv_kernel<<<(NN * KF / 4 + 255) / 256, 256>>>(feat);
    wconv_kernel<<<(HD * KF) / 256, 256>>>(W);
    hist_kernel<<<(EE + 255) / 256, 256>>>(dst);
    scan1_kernel<<<NSCB, 256>>>();
    scan2_kernel<<<1, 256>>>();
    scan3_kernel<<<NSCB, 256>>>();
    gemm_kernel<<<(NN + MTILE - 1) / MTILE, 256, smem_bytes>>>(attn_l, attn_r);
    sced_kernel<<<(EE + 255) / 256, 256>>>(src, dst);
    spmm_kernel<<<NN, 128>>>(out, bias);
}

// round 11
// speedup vs baseline: 2.1175x; 1.0937x over previous
#include <cuda_runtime.h>
#include <cuda_bf16.h>
#include <cstdint>

#define NN 50000
#define EE 800000
#define KF 256          // IN_FEATS
#define HH 4
#define HD 128          // H*D
#define NH 200000       // N*H
#define MTILE 128
#define KC 64           // K chunk
#define NCHUNK (KF / KC)
#define NSCB 196        // scan blocks = ceil(NN/256)

// smem layout (gemm): [0,128K) full B hi/lo ; [128K,160K) A tile hi/lo
#define B_BYTES 131072
#define A_TILE_BYTES 32768

// ---------------- scratch (device globals; no allocation) ----------------
__device__ float g_ft[NN * HD];
__device__ float g_el[NH];
__device__ float g_er[NH];
__device__ int   g_srcs[EE];         // src node ids, CSR-sorted by dst
__device__ int   g_deg[NN];
__device__ int   g_rank[EE];         // rank of edge within its dst segment
__device__ int   g_rowstart[NN + 1];
__device__ int   g_bsum[NSCB];
__device__ int   g_boff[NSCB];
__device__ __nv_bfloat16 g_wt_hi[HD * KF];   // W^T split-high  [n][k]
__device__ __nv_bfloat16 g_wt_lo[HD * KF];   // W^T split-low   [n][k]

// ---------------- helpers ----------------
__device__ __forceinline__ uint32_t smem_u32(const void* p) {
    uint32_t a;
    asm("{ .reg .u64 t; cvta.to.shared.u64 t, %1; cvt.u32.u64 %0, t; }" : "=r"(a) : "l"(p));
    return a;
}

#define SW128(o) ((o) ^ (((o) >> 3) & 0x70))

__device__ __forceinline__ void ldm_x4(uint32_t* r, uint32_t addr) {
    asm volatile("ldmatrix.sync.aligned.m8n8.x4.shared.b16 {%0,%1,%2,%3}, [%4];"
                 : "=r"(r[0]), "=r"(r[1]), "=r"(r[2]), "=r"(r[3]) : "r"(addr));
}

__device__ __forceinline__ void mma16816(float* c, const uint32_t* a, const uint32_t* b) {
    asm volatile(
        "mma.sync.aligned.m16n8k16.row.col.f32.bf16.bf16.f32 "
        "{%0,%1,%2,%3}, {%4,%5,%6,%7}, {%8,%9}, {%0,%1,%2,%3};"
        : "+f"(c[0]), "+f"(c[1]), "+f"(c[2]), "+f"(c[3])
        : "r"(a[0]), "r"(a[1]), "r"(a[2]), "r"(a[3]), "r"(b[0]), "r"(b[1]));
}

__device__ __forceinline__ void split_bf16(float x, unsigned short& h, unsigned short& l) {
    __nv_bfloat16 bh = __float2bfloat16(x);
    float r = x - __bfloat162float(bh);
    __nv_bfloat16 bl = __float2bfloat16(r);
    h = __bfloat16_as_ushort(bh);
    l = __bfloat16_as_ushort(bl);
}

// ---------------- init: zero deg ----------------
__global__ void init_kernel() {
    int i = blockIdx.x * blockDim.x + threadIdx.x;
    if (i < NN) g_deg[i] = 0;
}

// ---------------- W transpose + bf16 hi/lo split ----------------
__global__ void wconv_kernel(const float* __restrict__ W) {
    int idx = blockIdx.x * 256 + threadIdx.x;    // 0..32767
    int n = idx >> 8;
    int k = idx & 255;
    float w = W[k * HD + n];
    unsigned short h, l;
    split_bf16(w, h, l);
    g_wt_hi[n * KF + k] = __ushort_as_bfloat16(h);
    g_wt_lo[n * KF + k] = __ushort_as_bfloat16(l);
}

// ---------------- mma.sync bf16x3 GEMM: full-B smem, reg-prefetched A ----------------
__global__ void __launch_bounds__(256) gemm_kernel(const float* __restrict__ A,
                                                   const float* __restrict__ attn_l,
                                                   const float* __restrict__ attn_r) {
    extern __shared__ char smem[];
    const uint32_t sbase = smem_u32(smem);
    const uint32_t ubase = (sbase + 1023) & ~1023u;
    const uint32_t uB = ubase;                       // 128KB: hi 4x16KB, lo at +64KB
    const uint32_t uA_hi = ubase + B_BYTES;          // 16KB
    const uint32_t uA_lo = uA_hi + 16384;            // 16KB

    const int tid = threadIdx.x;
    const int wid = tid >> 5;
    const int lane = tid & 31;
    const int wm = wid & 3;
    const int wn = wid >> 2;
    const int block_row = blockIdx.x * MTILE;

    // ---- preload FULL B (hi+lo, 4 chunk tiles each) via cp.async ----
#pragma unroll
    for (int l = 0; l < 16; l++) {
        int q = tid + l * 256;              // 0..4095
        int kcb = q >> 10;                  // chunk tile 0..3
        int r = q & 1023;
        int row = r >> 3, c = r & 7;        // row 0..127, c = 16B col
        int gidx = row * KF + kcb * KC + c * 8;
        uint32_t off = kcb * 16384 + SW128((uint32_t)(row * 128 + c * 16));
        asm volatile("cp.async.cg.shared.global [%0], [%1], 16;"
                     :: "r"(uB + off), "l"(&g_wt_hi[gidx]));
        asm volatile("cp.async.cg.shared.global [%0], [%1], 16;"
                     :: "r"(uB + 65536 + off), "l"(&g_wt_lo[gidx]));
    }
    asm volatile("cp.async.commit_group;" ::: "memory");

    float acc[2][8][4];
#pragma unroll
    for (int i = 0; i < 2; i++)
#pragma unroll
        for (int j = 0; j < 8; j++)
#pragma unroll
            for (int q = 0; q < 4; q++) acc[i][j][q] = 0.0f;

    const int lrow = (lane & 7) + ((lane >> 3) & 1) * 8;
    const int lkh  = (lane >> 4) * 16;
    const int arow_base = (tid >> 4);       // row this thread loads: q>>4 with l stride 16
    const int ac4 = tid & 15;               // float4 col

    // ---- prefetch A chunk 0 to regs ----
    float4 a_cur[8], a_nxt[8];
#pragma unroll
    for (int l = 0; l < 8; l++) {
        int row = arow_base + l * 16;
        int grow = block_row + row;
        a_cur[l] = (grow < NN) ? *(const float4*)&A[grow * KF + ac4 * 4]
                               : make_float4(0.f, 0.f, 0.f, 0.f);
    }
    asm volatile("cp.async.wait_group 0;" ::: "memory");

    for (int kc = 0; kc < NCHUNK; kc++) {
        // issue prefetch of next chunk
        if (kc + 1 < NCHUNK) {
#pragma unroll
            for (int l = 0; l < 8; l++) {
                int row = arow_base + l * 16;
                int grow = block_row + row;
                a_nxt[l] = (grow < NN) ? *(const float4*)&A[grow * KF + (kc + 1) * KC + ac4 * 4]
                                       : make_float4(0.f, 0.f, 0.f, 0.f);
            }
        }
        // split current chunk to bf16 hi/lo smem
#pragma unroll
        for (int l = 0; l < 8; l++) {
            int row = arow_base + l * 16;
            float4 v = a_cur[l];
            unsigned short h0, h1, h2, h3, l0, l1, l2, l3;
            split_bf16(v.x, h0, l0); split_bf16(v.y, h1, l1);
            split_bf16(v.z, h2, l2); split_bf16(v.w, h3, l3);
            uint32_t off = SW128((uint32_t)(row * 128 + ac4 * 8));
            *(uint2*)(smem + (uA_hi - sbase) + off) =
                make_uint2(((uint32_t)h1 << 16) | h0, ((uint32_t)h3 << 16) | h2);
            *(uint2*)(smem + (uA_lo - sbase) + off) =
                make_uint2(((uint32_t)l1 << 16) | l0, ((uint32_t)l3 << 16) | l2);
        }
        __syncthreads();

        const uint32_t uB_hi = uB + kc * 16384;
        const uint32_t uB_lo = uB + 65536 + kc * 16384;
#pragma unroll
        for (int ks = 0; ks < 4; ks++) {
            const int kb = ks * 32;

            uint32_t ah[2][4], al[2][4];
#pragma unroll
            for (int mt = 0; mt < 2; mt++) {
                int arow = wm * 32 + mt * 16 + lrow;
                uint32_t aoff = SW128((uint32_t)(arow * 128 + kb + lkh));
                ldm_x4(ah[mt], uA_hi + aoff);
                ldm_x4(al[mt], uA_lo + aoff);
            }

#pragma unroll
            for (int np = 0; np < 4; np++) {
                int brow = wn * 64 + np * 16 + ((lane >> 4) * 8) + (lane & 7);
                uint32_t boff = SW128((uint32_t)(brow * 128 + kb + (((lane >> 3) & 1) * 16)));
                uint32_t bh[4], bl[4];
                ldm_x4(bh, uB_hi + boff);
#pragma unroll
                for (int mt = 0; mt < 2; mt++) {
                    mma16816(acc[mt][np * 2 + 0], ah[mt], bh + 0);
                    mma16816(acc[mt][np * 2 + 1], ah[mt], bh + 2);
                    mma16816(acc[mt][np * 2 + 0], al[mt], bh + 0);
                    mma16816(acc[mt][np * 2 + 1], al[mt], bh + 2);
                }
                ldm_x4(bl, uB_lo + boff);
#pragma unroll
                for (int mt = 0; mt < 2; mt++) {
                    mma16816(acc[mt][np * 2 + 0], ah[mt], bl + 0);
                    mma16816(acc[mt][np * 2 + 1], ah[mt], bl + 2);
                }
            }
        }
        __syncthreads();
#pragma unroll
        for (int l = 0; l < 8; l++) a_cur[l] = a_nxt[l];
    }

    // --- epilogue: store g_ft + fused el/er ---
    const int qrow = lane >> 2;
    const int qcol = (lane & 3) * 2;
    float elp[4][2], erp[4][2];
#pragma unroll
    for (int i = 0; i < 4; i++) { elp[i][0] = elp[i][1] = 0.f; erp[i][0] = erp[i][1] = 0.f; }

#pragma unroll
    for (int nt = 0; nt < 8; nt++) {
        int col = wn * 64 + nt * 8 + qcol;
        int hloc = nt >> 2;
        float wl0 = attn_l[col], wl1 = attn_l[col + 1];
        float wr0 = attn_r[col], wr1 = attn_r[col + 1];
#pragma unroll
        for (int mt = 0; mt < 2; mt++) {
            int r0 = block_row + wm * 32 + mt * 16 + qrow;
            float c0 = acc[mt][nt][0], c1 = acc[mt][nt][1];
            float c2 = acc[mt][nt][2], c3 = acc[mt][nt][3];
            if (r0 < NN) *(float2*)&g_ft[r0 * HD + col] = make_float2(c0, c1);
            if (r0 + 8 < NN) *(float2*)&g_ft[(r0 + 8) * HD + col] = make_float2(c2, c3);
            elp[mt * 2 + 0][hloc] += c0 * wl0 + c1 * wl1;
            erp[mt * 2 + 0][hloc] += c0 * wr0 + c1 * wr1;
            elp[mt * 2 + 1][hloc] += c2 * wl0 + c3 * wl1;
            erp[mt * 2 + 1][hloc] += c2 * wr0 + c3 * wr1;
        }
    }
#pragma unroll
    for (int o = 1; o <= 2; o <<= 1) {
#pragma unroll
        for (int i = 0; i < 4; i++) {
#pragma unroll
            for (int hl = 0; hl < 2; hl++) {
                elp[i][hl] += __shfl_xor_sync(0xffffffffu, elp[i][hl], o);
                erp[i][hl] += __shfl_xor_sync(0xffffffffu, erp[i][hl], o);
            }
        }
    }
    if ((lane & 3) == 0) {
        int hbase = wn * 2;
#pragma unroll
        for (int mt = 0; mt < 2; mt++) {
#pragma unroll
            for (int rh = 0; rh < 2; rh++) {
                int n = block_row + wm * 32 + mt * 16 + qrow + rh * 8;
                if (n < NN) {
                    g_el[n * HH + hbase]     = elp[mt * 2 + rh][0];
                    g_er[n * HH + hbase]     = erp[mt * 2 + rh][0];
                    g_el[n * HH + hbase + 1] = elp[mt * 2 + rh][1];
                    g_er[n * HH + hbase + 1] = erp[mt * 2 + rh][1];
                }
            }
        }
    }
}

// ---------------- degree histogram (keeps per-edge rank) ----------------
__global__ void hist_kernel(const int* __restrict__ dst) {
    int e = blockIdx.x * blockDim.x + threadIdx.x;
    if (e < EE) g_rank[e] = atomicAdd(&g_deg[dst[e]], 1);
}

// ---------------- hierarchical scan: 3 small wide kernels ----------------
__global__ void scan1_kernel() {
    __shared__ int sh[256];
    int t = threadIdx.x;
    int idx = blockIdx.x * 256 + t;
    int v = (idx < NN) ? g_deg[idx] : 0;
    sh[t] = v;
    __syncthreads();
#pragma unroll
    for (int d = 1; d < 256; d <<= 1) {
        int a = (t >= d) ? sh[t - d] : 0;
        __syncthreads();
        sh[t] += a;
        __syncthreads();
    }
    if (idx < NN) g_rowstart[idx] = sh[t] - v;
    if (t == 255) g_bsum[blockIdx.x] = sh[255];
}

__global__ void scan2_kernel() {
    __shared__ int sh[256];
    int t = threadIdx.x;
    int v = (t < NSCB) ? g_bsum[t] : 0;
    sh[t] = v;
    __syncthreads();
#pragma unroll
    for (int d = 1; d < 256; d <<= 1) {
        int a = (t >= d) ? sh[t - d] : 0;
        __syncthreads();
        sh[t] += a;
        __syncthreads();
    }
    if (t < NSCB) g_boff[t] = sh[t] - v;
}

__global__ void scan3_kernel() {
    int idx = blockIdx.x * 256 + threadIdx.x;
    if (idx < NN) g_rowstart[idx] += g_boff[blockIdx.x];
    if (idx == 0) g_rowstart[NN] = EE;
}

// ---------------- scatter src ids into CSR order (atomic-free) ----------------
__global__ void sced_kernel(const int* __restrict__ src, const int* __restrict__ dst) {
    int e = blockIdx.x * blockDim.x + threadIdx.x;
    if (e >= EE) return;
    g_srcs[g_rowstart[dst[e]] + g_rank[e]] = src[e];
}

// ---------------- SpMM: dst-centric, fused edge softmax, atomic-free ----------------
__global__ void spmm_kernel(float* __restrict__ out, const float* __restrict__ bias) {
    int n = blockIdx.x;
    int h = threadIdx.x >> 5;
    int lane = threadIdx.x & 31;
    int rs = g_rowstart[n], re = g_rowstart[n + 1];
    int off = h * 32 + lane;
    float er_h = g_er[n * HH + h];
    float acc = 0.f;
    float ssum = 0.f;
    for (int base = rs; base < re; base += 32) {
        int cnt = re - base;
        if (cnt > 32) cnt = 32;
        int sn = 0;
        float av = 0.f;
        if (lane < cnt) {
            sn = g_srcs[base + lane];
            float x = g_el[sn * HH + h] + er_h;
            x = (x > 0.f) ? x : 0.2f * x;
            av = __expf(x);
        }
        for (int j0 = 0; j0 < cnt; j0 += 8) {
#pragma unroll
            for (int jj = 0; jj < 8; jj++) {
                int j = j0 + jj;
                int snj = __shfl_sync(0xffffffffu, sn, j);
                float aj = __shfl_sync(0xffffffffu, av, j);
                acc += g_ft[snj * HD + off] * aj;   // aj==0 past cnt
                ssum += aj;
            }
        }
    }
    float invs = (re > rs) ? (1.0f / ssum) : 0.f;
    out[n * HD + off] = acc * invs + bias[off];
}

// ---------------- launch ----------------
extern "C" void kernel_launch(void* const* d_in, const int* in_sizes, int n_in,
                              void* d_out, int out_size) {
    const float* feat   = (const float*)d_in[0];
    const int*   src    = (const int*)  d_in[1];
    const int*   dst    = (const int*)  d_in[2];
    const float* W      = (const float*)d_in[3];
    const float* attn_l = (const float*)d_in[4];
    const float* attn_r = (const float*)d_in[5];
    const float* bias   = (const float*)d_in[6];
    float* out = (float*)d_out;

    const int smem_bytes = B_BYTES + A_TILE_BYTES + 1024 + 64;   // ~161KB
    cudaFuncSetAttribute(gemm_kernel, cudaFuncAttributeMaxDynamicSharedMemorySize, smem_bytes);

    init_kernel<<<(NN + 255) / 256, 256>>>();
    wconv_kernel<<<(HD * KF) / 256, 256>>>(W);
    hist_kernel<<<(EE + 255) / 256, 256>>>(dst);
    scan1_kernel<<<NSCB, 256>>>();
    scan2_kernel<<<1, 256>>>();
    scan3_kernel<<<NSCB, 256>>>();
    gemm_kernel<<<(NN + MTILE - 1) / MTILE, 256, smem_bytes>>>(feat, attn_l, attn_r);
    sced_kernel<<<(EE + 255) / 256, 256>>>(src, dst);
    spmm_kernel<<<NN, 128>>>(out, bias);
}

// round 12
// speedup vs baseline: 2.2857x; 1.0794x over previous
#include <cuda_runtime.h>
#include <cuda_bf16.h>
#include <cstdint>

#define NN 50000
#define EE 800000
#define KF 256          // IN_FEATS
#define HH 4
#define HD 128          // H*D
#define NH 200000       // N*H
#define MTILE 64
#define KC 64           // K chunk
#define NCHUNK (KF / KC)
#define NSCB 196        // scan blocks = ceil(NN/256)

// gemm smem: A bf16 hi/lo (2x8KB) + 2-stage B hi/lo (2x32KB) = 80KB
#define A_HI_OFF 0
#define A_LO_OFF 8192
#define STG_OFF  16384
#define STG_SIZE 32768   // hi 16KB + lo 16KB

// ---------------- scratch (device globals; no allocation) ----------------
__device__ float g_ft[NN * HD];
__device__ float g_el[NH];
__device__ float g_er[NH];
__device__ int   g_srcs[EE];         // src node ids, CSR-sorted by dst
__device__ int   g_deg[NN];
__device__ int   g_rank[EE];         // rank of edge within its dst segment
__device__ int   g_rowstart[NN + 1];
__device__ int   g_bsum[NSCB];
__device__ int   g_boff[NSCB];
__device__ __nv_bfloat16 g_wt_hi[HD * KF];   // W^T split-high  [n][k]
__device__ __nv_bfloat16 g_wt_lo[HD * KF];   // W^T split-low   [n][k]

// ---------------- helpers ----------------
__device__ __forceinline__ uint32_t smem_u32(const void* p) {
    uint32_t a;
    asm("{ .reg .u64 t; cvta.to.shared.u64 t, %1; cvt.u32.u64 %0, t; }" : "=r"(a) : "l"(p));
    return a;
}

#define SW128(o) ((o) ^ (((o) >> 3) & 0x70))

__device__ __forceinline__ void ldm_x4(uint32_t* r, uint32_t addr) {
    asm volatile("ldmatrix.sync.aligned.m8n8.x4.shared.b16 {%0,%1,%2,%3}, [%4];"
                 : "=r"(r[0]), "=r"(r[1]), "=r"(r[2]), "=r"(r[3]) : "r"(addr));
}

__device__ __forceinline__ void mma16816(float* c, const uint32_t* a, const uint32_t* b) {
    asm volatile(
        "mma.sync.aligned.m16n8k16.row.col.f32.bf16.bf16.f32 "
        "{%0,%1,%2,%3}, {%4,%5,%6,%7}, {%8,%9}, {%0,%1,%2,%3};"
        : "+f"(c[0]), "+f"(c[1]), "+f"(c[2]), "+f"(c[3])
        : "r"(a[0]), "r"(a[1]), "r"(a[2]), "r"(a[3]), "r"(b[0]), "r"(b[1]));
}

__device__ __forceinline__ void split_bf16(float x, unsigned short& h, unsigned short& l) {
    __nv_bfloat16 bh = __float2bfloat16(x);
    float r = x - __bfloat162float(bh);
    __nv_bfloat16 bl = __float2bfloat16(r);
    h = __bfloat16_as_ushort(bh);
    l = __bfloat16_as_ushort(bl);
}

// ---------------- init: zero deg ----------------
__global__ void init_kernel() {
    int i = blockIdx.x * blockDim.x + threadIdx.x;
    if (i < NN) g_deg[i] = 0;
}

// ---------------- W transpose + bf16 hi/lo split ----------------
__global__ void wconv_kernel(const float* __restrict__ W) {
    int idx = blockIdx.x * 256 + threadIdx.x;    // 0..32767
    int n = idx >> 8;
    int k = idx & 255;
    float w = W[k * HD + n];
    unsigned short h, l;
    split_bf16(w, h, l);
    g_wt_hi[n * KF + k] = __ushort_as_bfloat16(h);
    g_wt_lo[n * KF + k] = __ushort_as_bfloat16(l);
}

// ---------------- B stage fill via cp.async ----------------
__device__ __forceinline__ void issue_b(int kc, uint32_t stg, int tid) {
#pragma unroll
    for (int l = 0; l < 4; l++) {
        int q = tid + l * 256;              // 0..1023
        int row = q >> 3, c = q & 7;        // n row 0..127, 16B col
        int gidx = row * KF + kc * KC + c * 8;
        uint32_t off = SW128((uint32_t)(row * 128 + c * 16));
        asm volatile("cp.async.cg.shared.global [%0], [%1], 16;"
                     :: "r"(stg + off), "l"(&g_wt_hi[gidx]));
        asm volatile("cp.async.cg.shared.global [%0], [%1], 16;"
                     :: "r"(stg + 16384 + off), "l"(&g_wt_lo[gidx]));
    }
    asm volatile("cp.async.commit_group;" ::: "memory");
}

// ---------------- mma.sync bf16x3 GEMM: m64 CTA, 2 CTA/SM ----------------
__global__ void __launch_bounds__(256, 2) gemm_kernel(const float* __restrict__ A,
                                                      const float* __restrict__ attn_l,
                                                      const float* __restrict__ attn_r) {
    extern __shared__ char smem[];
    const uint32_t sbase = smem_u32(smem);
    const uint32_t ubase = (sbase + 1023) & ~1023u;
    const uint32_t uA_hi = ubase + A_HI_OFF;
    const uint32_t uA_lo = ubase + A_LO_OFF;

    const int tid = threadIdx.x;
    const int wid = tid >> 5;
    const int lane = tid & 31;
    const int wm = wid & 3;        // 4 m groups of 16 rows
    const int wn = wid >> 2;       // 2 n groups of 64 cols
    const int block_row = blockIdx.x * MTILE;

    // prefetch B chunk 0
    issue_b(0, ubase + STG_OFF, tid);

    float acc[8][4];
#pragma unroll
    for (int j = 0; j < 8; j++)
#pragma unroll
        for (int q = 0; q < 4; q++) acc[j][q] = 0.0f;

    const int lrow = (lane & 7) + ((lane >> 3) & 1) * 8;
    const int lkh  = (lane >> 4) * 16;
    const int arow_base = tid >> 4;     // 0..15 (+ l*16 -> 0..63)
    const int ac4 = tid & 15;

    // prefetch A chunk 0 into regs
    float4 a_cur[4];
#pragma unroll
    for (int l = 0; l < 4; l++) {
        int grow = block_row + arow_base + l * 16;
        a_cur[l] = (grow < NN) ? *(const float4*)&A[grow * KF + ac4 * 4]
                               : make_float4(0.f, 0.f, 0.f, 0.f);
    }

    for (int kc = 0; kc < NCHUNK; kc++) {
        // split current A chunk to bf16 hi/lo smem
#pragma unroll
        for (int l = 0; l < 4; l++) {
            int row = arow_base + l * 16;
            float4 v = a_cur[l];
            unsigned short h0, h1, h2, h3, l0, l1, l2, l3;
            split_bf16(v.x, h0, l0); split_bf16(v.y, h1, l1);
            split_bf16(v.z, h2, l2); split_bf16(v.w, h3, l3);
            uint32_t off = SW128((uint32_t)(row * 128 + ac4 * 8));
            *(uint2*)(smem + (uA_hi - sbase) + off) =
                make_uint2(((uint32_t)h1 << 16) | h0, ((uint32_t)h3 << 16) | h2);
            *(uint2*)(smem + (uA_lo - sbase) + off) =
                make_uint2(((uint32_t)l1 << 16) | l0, ((uint32_t)l3 << 16) | l2);
        }
        // prefetch next A chunk (regs free after split; hides under MMA loop)
        if (kc + 1 < NCHUNK) {
#pragma unroll
            for (int l = 0; l < 4; l++) {
                int grow = block_row + arow_base + l * 16;
                a_cur[l] = (grow < NN)
                    ? *(const float4*)&A[grow * KF + (kc + 1) * KC + ac4 * 4]
                    : make_float4(0.f, 0.f, 0.f, 0.f);
            }
            issue_b(kc + 1, ubase + STG_OFF + ((kc + 1) & 1) * STG_SIZE, tid);
            asm volatile("cp.async.wait_group 1;" ::: "memory");
        } else {
            asm volatile("cp.async.wait_group 0;" ::: "memory");
        }
        __syncthreads();

        const uint32_t uB_hi = ubase + STG_OFF + (kc & 1) * STG_SIZE;
        const uint32_t uB_lo = uB_hi + 16384;
#pragma unroll
        for (int ks = 0; ks < 4; ks++) {
            const int kb = ks * 32;

            uint32_t ah[4], al[4];
            int arow = wm * 16 + lrow;
            uint32_t aoff = SW128((uint32_t)(arow * 128 + kb + lkh));
            ldm_x4(ah, uA_hi + aoff);
            ldm_x4(al, uA_lo + aoff);

#pragma unroll
            for (int np = 0; np < 4; np++) {
                int brow = wn * 64 + np * 16 + ((lane >> 4) * 8) + (lane & 7);
                uint32_t boff = SW128((uint32_t)(brow * 128 + kb + (((lane >> 3) & 1) * 16)));
                uint32_t bh[4], bl[4];
                ldm_x4(bh, uB_hi + boff);
                mma16816(acc[np * 2 + 0], ah, bh + 0);
                mma16816(acc[np * 2 + 1], ah, bh + 2);
                mma16816(acc[np * 2 + 0], al, bh + 0);
                mma16816(acc[np * 2 + 1], al, bh + 2);
                ldm_x4(bl, uB_lo + boff);
                mma16816(acc[np * 2 + 0], ah, bl + 0);
                mma16816(acc[np * 2 + 1], ah, bl + 2);
            }
        }
        __syncthreads();
    }

    // --- epilogue: store g_ft + fused el/er ---
    const int qrow = lane >> 2;          // 0..7
    const int qcol = (lane & 3) * 2;
    float elp[2][2], erp[2][2];          // [row-half rh][head-local]
#pragma unroll
    for (int i = 0; i < 2; i++) { elp[i][0] = elp[i][1] = 0.f; erp[i][0] = erp[i][1] = 0.f; }

#pragma unroll
    for (int nt = 0; nt < 8; nt++) {
        int col = wn * 64 + nt * 8 + qcol;
        int hloc = nt >> 2;
        float wl0 = attn_l[col], wl1 = attn_l[col + 1];
        float wr0 = attn_r[col], wr1 = attn_r[col + 1];
        int r0 = block_row + wm * 16 + qrow;
        float c0 = acc[nt][0], c1 = acc[nt][1], c2 = acc[nt][2], c3 = acc[nt][3];
        if (r0 < NN) *(float2*)&g_ft[r0 * HD + col] = make_float2(c0, c1);
        if (r0 + 8 < NN) *(float2*)&g_ft[(r0 + 8) * HD + col] = make_float2(c2, c3);
        elp[0][hloc] += c0 * wl0 + c1 * wl1;
        erp[0][hloc] += c0 * wr0 + c1 * wr1;
        elp[1][hloc] += c2 * wl0 + c3 * wl1;
        erp[1][hloc] += c2 * wr0 + c3 * wr1;
    }
#pragma unroll
    for (int o = 1; o <= 2; o <<= 1) {
#pragma unroll
        for (int i = 0; i < 2; i++) {
#pragma unroll
            for (int hl = 0; hl < 2; hl++) {
                elp[i][hl] += __shfl_xor_sync(0xffffffffu, elp[i][hl], o);
                erp[i][hl] += __shfl_xor_sync(0xffffffffu, erp[i][hl], o);
            }
        }
    }
    if ((lane & 3) == 0) {
        int hbase = wn * 2;
#pragma unroll
        for (int rh = 0; rh < 2; rh++) {
            int n = block_row + wm * 16 + qrow + rh * 8;
            if (n < NN) {
                g_el[n * HH + hbase]     = elp[rh][0];
                g_er[n * HH + hbase]     = erp[rh][0];
                g_el[n * HH + hbase + 1] = elp[rh][1];
                g_er[n * HH + hbase + 1] = erp[rh][1];
            }
        }
    }
}

// ---------------- degree histogram (keeps per-edge rank) ----------------
__global__ void hist_kernel(const int* __restrict__ dst) {
    int e = blockIdx.x * blockDim.x + threadIdx.x;
    if (e < EE) g_rank[e] = atomicAdd(&g_deg[dst[e]], 1);
}

// ---------------- hierarchical scan: 3 small wide kernels ----------------
__global__ void scan1_kernel() {
    __shared__ int sh[256];
    int t = threadIdx.x;
    int idx = blockIdx.x * 256 + t;
    int v = (idx < NN) ? g_deg[idx] : 0;
    sh[t] = v;
    __syncthreads();
#pragma unroll
    for (int d = 1; d < 256; d <<= 1) {
        int a = (t >= d) ? sh[t - d] : 0;
        __syncthreads();
        sh[t] += a;
        __syncthreads();
    }
    if (idx < NN) g_rowstart[idx] = sh[t] - v;
    if (t == 255) g_bsum[blockIdx.x] = sh[255];
}

__global__ void scan2_kernel() {
    __shared__ int sh[256];
    int t = threadIdx.x;
    int v = (t < NSCB) ? g_bsum[t] : 0;
    sh[t] = v;
    __syncthreads();
#pragma unroll
    for (int d = 1; d < 256; d <<= 1) {
        int a = (t >= d) ? sh[t - d] : 0;
        __syncthreads();
        sh[t] += a;
        __syncthreads();
    }
    if (t < NSCB) g_boff[t] = sh[t] - v;
}

__global__ void scan3_kernel() {
    int idx = blockIdx.x * 256 + threadIdx.x;
    if (idx < NN) g_rowstart[idx] += g_boff[blockIdx.x];
    if (idx == 0) g_rowstart[NN] = EE;
}

// ---------------- scatter src ids into CSR order (atomic-free) ----------------
__global__ void sced_kernel(const int* __restrict__ src, const int* __restrict__ dst) {
    int e = blockIdx.x * blockDim.x + threadIdx.x;
    if (e >= EE) return;
    g_srcs[g_rowstart[dst[e]] + g_rank[e]] = src[e];
}

// ---------------- SpMM: dst-centric, fused edge softmax, atomic-free ----------------
__global__ void spmm_kernel(float* __restrict__ out, const float* __restrict__ bias) {
    int n = blockIdx.x;
    int h = threadIdx.x >> 5;
    int lane = threadIdx.x & 31;
    int rs = g_rowstart[n], re = g_rowstart[n + 1];
    int off = h * 32 + lane;
    float er_h = g_er[n * HH + h];
    float acc = 0.f;
    float ssum = 0.f;
    for (int base = rs; base < re; base += 32) {
        int cnt = re - base;
        if (cnt > 32) cnt = 32;
        int sn = 0;
        float av = 0.f;
        if (lane < cnt) {
            sn = g_srcs[base + lane];
            float x = g_el[sn * HH + h] + er_h;
            x = (x > 0.f) ? x : 0.2f * x;
            av = __expf(x);
        }
        for (int j0 = 0; j0 < cnt; j0 += 8) {
#pragma unroll
            for (int jj = 0; jj < 8; jj++) {
                int j = j0 + jj;
                int snj = __shfl_sync(0xffffffffu, sn, j);
                float aj = __shfl_sync(0xffffffffu, av, j);
                acc += g_ft[snj * HD + off] * aj;   // aj==0 past cnt
                ssum += aj;
            }
        }
    }
    float invs = (re > rs) ? (1.0f / ssum) : 0.f;
    out[n * HD + off] = acc * invs + bias[off];
}

// ---------------- launch ----------------
extern "C" void kernel_launch(void* const* d_in, const int* in_sizes, int n_in,
                              void* d_out, int out_size) {
    const float* feat   = (const float*)d_in[0];
    const int*   src    = (const int*)  d_in[1];
    const int*   dst    = (const int*)  d_in[2];
    const float* W      = (const float*)d_in[3];
    const float* attn_l = (const float*)d_in[4];
    const float* attn_r = (const float*)d_in[5];
    const float* bias   = (const float*)d_in[6];
    float* out = (float*)d_out;

    const int smem_bytes = STG_OFF + 2 * STG_SIZE + 1024 + 64;   // ~81KB
    cudaFuncSetAttribute(gemm_kernel, cudaFuncAttributeMaxDynamicSharedMemorySize, smem_bytes);

    init_kernel<<<(NN + 255) / 256, 256>>>();
    wconv_kernel<<<(HD * KF) / 256, 256>>>(W);
    hist_kernel<<<(EE + 255) / 256, 256>>>(dst);
    scan1_kernel<<<NSCB, 256>>>();
    scan2_kernel<<<1, 256>>>();
    scan3_kernel<<<NSCB, 256>>>();
    gemm_kernel<<<(NN + MTILE - 1) / MTILE, 256, smem_bytes>>>(feat, attn_l, attn_r);
    sced_kernel<<<(EE + 255) / 256, 256>>>(src, dst);
    spmm_kernel<<<NN, 128>>>(out, bias);
}